// round 10
// baseline (speedup 1.0000x reference)
#include <cuda_runtime.h>
#include <cuda_bf16.h>
#include <cstdint>
#include <math.h>

#define D_MODEL 1024
#define N_HEADS 16
#define HEAD_DIM 64
#define BATCH 2
#define SEQ 2048
#define M_TOT (BATCH * SEQ)   // 4096
#define WN (D_MODEL * D_MODEL)

// ---------------- scratch (no allocations allowed) ----------------
__device__ __nv_bfloat16 g_x_hi[M_TOT * D_MODEL];
__device__ __nv_bfloat16 g_x_lo[M_TOT * D_MODEL];
__device__ __nv_bfloat16 g_w_hi[4 * WN];   // wq,wk,wv,wo
__device__ __nv_bfloat16 g_w_lo[4 * WN];
__device__ __nv_bfloat16 g_qh[M_TOT * D_MODEL], g_ql[M_TOT * D_MODEL];   // [b,h,s,d]
__device__ __nv_bfloat16 g_kh[M_TOT * D_MODEL], g_kl[M_TOT * D_MODEL];   // [b,h,s,d]
__device__ __nv_bfloat16 g_vth[M_TOT * D_MODEL], g_vtl[M_TOT * D_MODEL]; // [h*64+d][b*2048+s]
__device__ __nv_bfloat16 g_ah[M_TOT * D_MODEL], g_al[M_TOT * D_MODEL];   // [m][1024]

// =================== portable PTX helpers ===================
__device__ __forceinline__ uint32_t smem_u32(const void* p) {
    uint32_t a;
    asm("{ .reg .u64 t; cvta.to.shared.u64 t, %1; cvt.u32.u64 %0, t; }"
        : "=r"(a) : "l"(p));
    return a;
}

__device__ __forceinline__ void ldsm_x4(uint32_t* r, uint32_t addr) {
    asm volatile("ldmatrix.sync.aligned.m8n8.x4.shared.b16 {%0,%1,%2,%3}, [%4];"
                 : "=r"(r[0]), "=r"(r[1]), "=r"(r[2]), "=r"(r[3]) : "r"(addr));
}

// D += A * B  (m16n8k16, bf16 in, fp32 acc)
__device__ __forceinline__ void mma_bf16(float* d, const uint32_t* a,
                                         uint32_t b0, uint32_t b1) {
    asm volatile(
        "mma.sync.aligned.m16n8k16.row.col.f32.bf16.bf16.f32 "
        "{%0,%1,%2,%3}, {%4,%5,%6,%7}, {%8,%9}, {%0,%1,%2,%3};"
        : "+f"(d[0]), "+f"(d[1]), "+f"(d[2]), "+f"(d[3])
        : "r"(a[0]), "r"(a[1]), "r"(a[2]), "r"(a[3]), "r"(b0), "r"(b1));
}

__device__ __forceinline__ void cp16(void* dst_smem, const void* src) {
    uint32_t d = smem_u32(dst_smem);
    asm volatile("cp.async.cg.shared.global [%0], [%1], 16;" :: "r"(d), "l"(src) : "memory");
}
#define CP_COMMIT() asm volatile("cp.async.commit_group;" ::: "memory")

__device__ __forceinline__ void pack_hl(float v0, float v1, uint32_t& hi, uint32_t& lo) {
    __nv_bfloat162 h = __floats2bfloat162_rn(v0, v1);
    __nv_bfloat162 l = __floats2bfloat162_rn(v0 - __bfloat162float(h.x),
                                             v1 - __bfloat162float(h.y));
    hi = *(uint32_t*)&h;
    lo = *(uint32_t*)&l;
}
__device__ __forceinline__ void store_pair(__nv_bfloat16* Oh, __nv_bfloat16* Ol,
                                           size_t off, float v0, float v1) {
    __nv_bfloat162 h = __floats2bfloat162_rn(v0, v1);
    __nv_bfloat162 l = __floats2bfloat162_rn(v0 - __bfloat162float(h.x),
                                             v1 - __bfloat162float(h.y));
    *(__nv_bfloat162*)(Oh + off) = h;
    *(__nv_bfloat162*)(Ol + off) = l;
}

// =================================================================
// fused split: x (1M float4) + 4 weights (256K float4 each) -> hi/lo
// =================================================================
#define XF4 (M_TOT * D_MODEL / 4)   // 1048576
#define WF4 (WN / 4)                // 262144

__global__ __launch_bounds__(256)
void split_all(const float* __restrict__ x, const float* __restrict__ wq,
               const float* __restrict__ wk, const float* __restrict__ wv,
               const float* __restrict__ wo,
               __nv_bfloat16* __restrict__ xh, __nv_bfloat16* __restrict__ xl,
               __nv_bfloat16* __restrict__ wh, __nv_bfloat16* __restrict__ wl) {
    int i = blockIdx.x * 256 + threadIdx.x;
    const float* src;
    __nv_bfloat16 *hi, *lo;
    int off;
    if (i < XF4) {
        src = x; hi = xh; lo = xl; off = i;
    } else {
        int j = i - XF4;
        int w = j >> 18;            // /WF4
        off = j & (WF4 - 1);
        src = (w == 0) ? wq : (w == 1) ? wk : (w == 2) ? wv : wo;
        hi = wh + (size_t)w * WN;
        lo = wl + (size_t)w * WN;
    }
    float4 v = ((const float4*)src)[off];
    uint32_t h0, l0, h1, l1;
    pack_hl(v.x, v.y, h0, l0);
    pack_hl(v.z, v.w, h1, l1);
    ((uint2*)hi)[off] = make_uint2(h0, h1);
    ((uint2*)lo)[off] = make_uint2(l0, l1);
}

// =================================================================
// GEMM body: C tile [bm:bm+128, bn:bn+128] of A[.,1024] @ W[.,1024]^T
// bf16x3 compensated, cp.async 2-stage, software-pipelined fragments.
// MODE 0: fp32 row-major C (ldc)
// MODE 1: bf16 hi/lo -> [b,h,s,d] head layout
// MODE 3: bf16 hi/lo row-major (ldc)
// =================================================================
#define SROW 40                        // smem row stride in halves
#define STAGE_B (128 * SROW * 2)       // 10240 B per tile
#define GSTAGE (4 * STAGE_B)           // 40960 B per stage
#define GEMM_SMEM (2 * GSTAGE)         // 81920 B

__device__ __forceinline__ void gemm_body(
    char* gsm,
    const __nv_bfloat16* __restrict__ Ahi, const __nv_bfloat16* __restrict__ Alo,
    const __nv_bfloat16* __restrict__ Whi, const __nv_bfloat16* __restrict__ Wlo,
    float* __restrict__ C, __nv_bfloat16* __restrict__ Oh,
    __nv_bfloat16* __restrict__ Ol, int ldc, int MODE, int bm, int bn) {
    const int tid = threadIdx.x;
    const int wid = tid >> 5, lane = tid & 31;
    const int wm = wid >> 1, wn = wid & 1;   // unused placeholder (kept layout below)
    (void)wm; (void)wn;
    const int wmr = wid >> 2, wnr = wid & 3;

    float acc[4][4][4];
#pragma unroll
    for (int i = 0; i < 4; i++)
#pragma unroll
        for (int j = 0; j < 4; j++)
#pragma unroll
            for (int r = 0; r < 4; r++) acc[i][j][r] = 0.f;

    const int lrow = lane & 15, lcol = (lane >> 4) * 8;

    auto fill = [&](int st, int k0) {
        char* base = gsm + st * GSTAGE;
#pragma unroll
        for (int i = 0; i < 2; i++) {
            int c = tid + i * 256;
            int row = c >> 2, kc = (c & 3) * 8;
            int so = (row * SROW + kc) * 2;
            size_t ga = (size_t)(bm + row) * 1024 + k0 + kc;
            size_t gb = (size_t)(bn + row) * 1024 + k0 + kc;
            cp16(base + so, Ahi + ga);
            cp16(base + STAGE_B + so, Alo + ga);
            cp16(base + 2 * STAGE_B + so, Whi + gb);
            cp16(base + 3 * STAGE_B + so, Wlo + gb);
        }
        CP_COMMIT();
    };

    fill(0, 0);
    for (int ch = 0; ch < 32; ch++) {
        if (ch + 1 < 32) {
            fill((ch + 1) & 1, (ch + 1) * 32);
            asm volatile("cp.async.wait_group 1;" ::: "memory");
        } else {
            asm volatile("cp.async.wait_group 0;" ::: "memory");
        }
        __syncthreads();
        char* base = gsm + (ch & 1) * GSTAGE;
        __nv_bfloat16* sAh = (__nv_bfloat16*)base;
        __nv_bfloat16* sAl = (__nv_bfloat16*)(base + STAGE_B);
        __nv_bfloat16* sBh = (__nv_bfloat16*)(base + 2 * STAGE_B);
        __nv_bfloat16* sBl = (__nv_bfloat16*)(base + 3 * STAGE_B);

#pragma unroll
        for (int ks = 0; ks < 32; ks += 16) {
            // B fragments (whole warp-N strip)
            uint32_t bh[2][4], bl[2][4];
#pragma unroll
            for (int p = 0; p < 2; p++) {
                int off = (wnr * 32 + p * 16 + lrow) * SROW + ks + lcol;
                ldsm_x4(bh[p], smem_u32(sBh + off));
                ldsm_x4(bl[p], smem_u32(sBl + off));
            }
            // A fragments: 2-deep pipeline, prefetch mi+1 during MMAs of mi
            uint32_t ah[2][4], al[2][4];
            {
                int off = (wmr * 64 + lrow) * SROW + ks + lcol;
                ldsm_x4(ah[0], smem_u32(sAh + off));
                ldsm_x4(al[0], smem_u32(sAl + off));
            }
#pragma unroll
            for (int mi = 0; mi < 4; mi++) {
                const int cur = mi & 1, nxt = cur ^ 1;
                if (mi < 3) {
                    int off = (wmr * 64 + (mi + 1) * 16 + lrow) * SROW + ks + lcol;
                    ldsm_x4(ah[nxt], smem_u32(sAh + off));
                    ldsm_x4(al[nxt], smem_u32(sAl + off));
                }
#pragma unroll
                for (int ni = 0; ni < 4; ni++) {
                    int p = ni >> 1, q = ni & 1;
                    mma_bf16(acc[mi][ni], ah[cur], bh[p][q], bh[p][q + 2]);
                    mma_bf16(acc[mi][ni], ah[cur], bl[p][q], bl[p][q + 2]);
                    mma_bf16(acc[mi][ni], al[cur], bh[p][q], bh[p][q + 2]);
                }
            }
        }
        __syncthreads();
    }

    // ---- epilogue ----
    const int r_in = lane >> 2, c_in = (lane & 3) * 2;
#pragma unroll
    for (int mi = 0; mi < 4; mi++) {
#pragma unroll
        for (int ni = 0; ni < 4; ni++) {
            int m0 = bm + wmr * 64 + mi * 16 + r_in;
            int n  = bn + wnr * 32 + ni * 8 + c_in;
            float v0 = acc[mi][ni][0], v1 = acc[mi][ni][1];
            float v2 = acc[mi][ni][2], v3 = acc[mi][ni][3];
            if (MODE == 0) {
                *(float2*)(C + (size_t)m0 * ldc + n) = make_float2(v0, v1);
                *(float2*)(C + (size_t)(m0 + 8) * ldc + n) = make_float2(v2, v3);
            } else if (MODE == 3) {
                store_pair(Oh, Ol, (size_t)m0 * ldc + n, v0, v1);
                store_pair(Oh, Ol, (size_t)(m0 + 8) * ldc + n, v2, v3);
            } else {  // MODE 1: [b,h,s,d]
                int h = n >> 6, d = n & 63;
#pragma unroll
                for (int rr = 0; rr < 2; rr++) {
                    int m = m0 + rr * 8;
                    int b = m >> 11, s = m & 2047;
                    size_t off = ((size_t)((b * N_HEADS + h) * SEQ + s)) * HEAD_DIM + d;
                    store_pair(Oh, Ol, off, acc[mi][ni][2 * rr], acc[mi][ni][2 * rr + 1]);
                }
            }
        }
    }
}

// fused Q/K/V projections: z=0 -> Q, z=1 -> K, z=2 -> V-transposed
__global__ __launch_bounds__(256, 2)
void qkv_gemm(const __nv_bfloat16* __restrict__ xh, const __nv_bfloat16* __restrict__ xl,
              const __nv_bfloat16* __restrict__ wh, const __nv_bfloat16* __restrict__ wl,
              __nv_bfloat16* __restrict__ qh, __nv_bfloat16* __restrict__ ql,
              __nv_bfloat16* __restrict__ kh, __nv_bfloat16* __restrict__ kl,
              __nv_bfloat16* __restrict__ vth, __nv_bfloat16* __restrict__ vtl) {
    extern __shared__ char gsm[];
    const int z = blockIdx.z;
    if (z == 0) {
        gemm_body(gsm, xh, xl, wh, wl, nullptr, qh, ql, 0, 1,
                  blockIdx.y * 128, blockIdx.x * 128);
    } else if (z == 1) {
        gemm_body(gsm, xh, xl, wh + WN, wl + WN, nullptr, kh, kl, 0, 1,
                  blockIdx.y * 128, blockIdx.x * 128);
    } else {
        // V transposed: C' = wv @ x^T -> [channel][token]
        gemm_body(gsm, wh + 2 * (size_t)WN, wl + 2 * (size_t)WN, xh, xl,
                  nullptr, vth, vtl, M_TOT, 3,
                  blockIdx.x * 128, blockIdx.y * 128);
    }
}

// output projection: fp32 row-major
__global__ __launch_bounds__(256, 2)
void o_gemm(const __nv_bfloat16* __restrict__ ah, const __nv_bfloat16* __restrict__ al,
            const __nv_bfloat16* __restrict__ wh, const __nv_bfloat16* __restrict__ wl,
            float* __restrict__ out) {
    extern __shared__ char gsm[];
    gemm_body(gsm, ah, al, wh, wl, out, nullptr, nullptr, D_MODEL, 0,
              blockIdx.y * 128, blockIdx.x * 128);
}

// =================================================================
// Flash attention on mma.sync, bf16x3 compensated, causal.
// CTA: 128 q rows x full head. 8 warps, warp = 16 q rows. Key tiles 64.
// cp.async 2-stage double-buffered K/V hi/lo tiles.
// Q-hi frags in registers; Q-lo in smem, re-materialized per tile.
// LPT: longest CTAs (high qt) launch first.
// =================================================================
#define ASROW 72
#define ABUF_B (64 * ASROW * 2)        // 9216 B per tile buffer
#define ASTAGE (4 * ABUF_B)            // 36864 B per stage
#define QL_B (128 * ASROW * 2)         // 18432 B for Q-lo
#define ATTN_SMEM (2 * ASTAGE + QL_B)  // 92160 B

__global__ __launch_bounds__(256, 2)
void attn_kernel(const __nv_bfloat16* __restrict__ Qh, const __nv_bfloat16* __restrict__ Ql,
                 const __nv_bfloat16* __restrict__ Kh, const __nv_bfloat16* __restrict__ Kl,
                 const __nv_bfloat16* __restrict__ Vh, const __nv_bfloat16* __restrict__ Vl,
                 __nv_bfloat16* __restrict__ Ohg, __nv_bfloat16* __restrict__ Olg) {
    extern __shared__ char asm_raw[];
    auto buf = [&](int st, int w) -> __nv_bfloat16* {
        return (__nv_bfloat16*)(asm_raw + st * ASTAGE + w * ABUF_B);
    };
    __nv_bfloat16* sQl = (__nv_bfloat16*)(asm_raw + 2 * ASTAGE);

    const int tid = threadIdx.x, wid = tid >> 5, lane = tid & 31;
    const int qt = (int)gridDim.x - 1 - (int)blockIdx.x;   // LPT: long CTAs first
    const int bh = blockIdx.y;
    const int b = bh >> 4, h = bh & 15;
    const int q0 = qt * 128;
    const size_t qkbase = (size_t)bh * SEQ * HEAD_DIM;
    const size_t vbase = (size_t)(h * 64) * 4096 + (size_t)b * 2048;

    const int lrow = lane & 15, lcol = (lane >> 4) * 8;
    const int rA = lane >> 2;
    const int tig2 = (lane & 3) * 2;
    const int qlrow = (wid * 16 + lrow) * ASROW;   // ldsm row base in sQl

    // ---- stage Q: lo -> dedicated smem; hi -> fragments via scratch ----
#pragma unroll
    for (int i = 0; i < 4; i++) {
        int c = tid + i * 256;
        int row = c >> 3, cc = (c & 7) * 8;
        *(uint4*)(sQl + row * ASROW + cc) =
            *(const uint4*)(Ql + qkbase + (size_t)(q0 + row) * 64 + cc);
        __nv_bfloat16* dst = buf(0, row < 64 ? 0 : 1) + (row & 63) * ASROW + cc;
        *(uint4*)dst = *(const uint4*)(Qh + qkbase + (size_t)(q0 + row) * 64 + cc);
    }
    __syncthreads();
    uint32_t qfh[4][4];
    {
        int qr = wid * 16 + lrow;
        const __nv_bfloat16* bq = buf(0, qr < 64 ? 0 : 1);
        int qrl = qr & 63;
#pragma unroll
        for (int ks = 0; ks < 4; ks++)
            ldsm_x4(qfh[ks], smem_u32(bq + qrl * ASROW + ks * 16 + lcol));
    }
    __syncthreads();   // scratch free before fillKV overwrites it

    auto fillKV = [&](int st, int k0) {
#pragma unroll
        for (int i = 0; i < 2; i++) {
            int c = tid + i * 256;
            int row = c >> 3, cc = (c & 7) * 8;
            int so = row * ASROW + cc;
            cp16(buf(st, 0) + so, Kh + qkbase + (size_t)(k0 + row) * 64 + cc);
            cp16(buf(st, 1) + so, Kl + qkbase + (size_t)(k0 + row) * 64 + cc);
            cp16(buf(st, 2) + so, Vh + vbase + (size_t)row * 4096 + k0 + cc);
            cp16(buf(st, 3) + so, Vl + vbase + (size_t)row * 4096 + k0 + cc);
        }
        CP_COMMIT();
    };

    float oacc[8][4];
#pragma unroll
    for (int i = 0; i < 8; i++)
#pragma unroll
        for (int j = 0; j < 4; j++) oacc[i][j] = 0.f;
    float mMA = -1e30f, mMB = -1e30f, lA = 0.f, lB = 0.f;

    const int nt = 2 * qt + 2;
    fillKV(0, 0);
    for (int jt = 0; jt < nt; jt++) {
        const int k0 = jt * 64;
        if (jt + 1 < nt) {
            fillKV((jt + 1) & 1, (jt + 1) * 64);
            asm volatile("cp.async.wait_group 1;" ::: "memory");
        } else {
            asm volatile("cp.async.wait_group 0;" ::: "memory");
        }
        __syncthreads();
        const int st = jt & 1;
        __nv_bfloat16* sKh = buf(st, 0);
        __nv_bfloat16* sKl = buf(st, 1);
        __nv_bfloat16* sVh = buf(st, 2);
        __nv_bfloat16* sVl = buf(st, 3);

        const int wrow0 = q0 + wid * 16;
        if (k0 <= wrow0 + 15) {
            // ---- scores S = Q K^T (3 compensated combos, pipelined K frags) ----
            float sacc[8][4];
#pragma unroll
            for (int i = 0; i < 8; i++)
#pragma unroll
                for (int j = 0; j < 4; j++) sacc[i][j] = 0.f;
#pragma unroll
            for (int ks = 0; ks < 4; ks++) {
                uint32_t qfl_t[4];
                ldsm_x4(qfl_t, smem_u32(sQl + qlrow + ks * 16 + lcol));
                uint32_t kfh[2][4], kfl[2][4];
                {
                    int off = lrow * ASROW + ks * 16 + lcol;   // p = 0
                    ldsm_x4(kfh[0], smem_u32(sKh + off));
                    ldsm_x4(kfl[0], smem_u32(sKl + off));
                }
#pragma unroll
                for (int p = 0; p < 4; p++) {
                    const int cur = p & 1, nxt = cur ^ 1;
                    if (p < 3) {
                        int off = ((p + 1) * 16 + lrow) * ASROW + ks * 16 + lcol;
                        ldsm_x4(kfh[nxt], smem_u32(sKh + off));
                        ldsm_x4(kfl[nxt], smem_u32(sKl + off));
                    }
#pragma unroll
                    for (int qq = 0; qq < 2; qq++) {
                        int ni = 2 * p + qq;
                        mma_bf16(sacc[ni], qfh[ks], kfh[cur][qq], kfh[cur][qq + 2]);
                        mma_bf16(sacc[ni], qfh[ks], kfl[cur][qq], kfl[cur][qq + 2]);
                        mma_bf16(sacc[ni], qfl_t, kfh[cur][qq], kfh[cur][qq + 2]);
                    }
                }
            }
            // ---- scale + causal mask ----
            const bool band = (k0 + 63 > wrow0);
            const int rowAg = wrow0 + rA, rowBg = rowAg + 8;
#pragma unroll
            for (int ni = 0; ni < 8; ni++) {
                int colb = k0 + ni * 8 + tig2;
#pragma unroll
                for (int e = 0; e < 4; e++) {
                    float s = sacc[ni][e] * 0.125f;
                    if (band) {
                        int col = colb + (e & 1);
                        int row = (e < 2) ? rowAg : rowBg;
                        if (col > row) s = -1e30f;
                    }
                    sacc[ni][e] = s;
                }
            }
            // ---- online softmax ----
            float mxA = -1e30f, mxB = -1e30f;
#pragma unroll
            for (int ni = 0; ni < 8; ni++) {
                mxA = fmaxf(mxA, fmaxf(sacc[ni][0], sacc[ni][1]));
                mxB = fmaxf(mxB, fmaxf(sacc[ni][2], sacc[ni][3]));
            }
            mxA = fmaxf(mxA, __shfl_xor_sync(0xffffffffu, mxA, 1));
            mxA = fmaxf(mxA, __shfl_xor_sync(0xffffffffu, mxA, 2));
            mxB = fmaxf(mxB, __shfl_xor_sync(0xffffffffu, mxB, 1));
            mxB = fmaxf(mxB, __shfl_xor_sync(0xffffffffu, mxB, 2));
            float mnA = fmaxf(mMA, mxA), mnB = fmaxf(mMB, mxB);
            float scA = __expf(mMA - mnA), scB = __expf(mMB - mnB);
            mMA = mnA; mMB = mnB;
            float suA = 0.f, suB = 0.f;
#pragma unroll
            for (int ni = 0; ni < 8; ni++) {
                sacc[ni][0] = __expf(sacc[ni][0] - mnA); suA += sacc[ni][0];
                sacc[ni][1] = __expf(sacc[ni][1] - mnA); suA += sacc[ni][1];
                sacc[ni][2] = __expf(sacc[ni][2] - mnB); suB += sacc[ni][2];
                sacc[ni][3] = __expf(sacc[ni][3] - mnB); suB += sacc[ni][3];
            }
            suA += __shfl_xor_sync(0xffffffffu, suA, 1);
            suA += __shfl_xor_sync(0xffffffffu, suA, 2);
            suB += __shfl_xor_sync(0xffffffffu, suB, 1);
            suB += __shfl_xor_sync(0xffffffffu, suB, 2);
            lA = lA * scA + suA;
            lB = lB * scB + suB;
#pragma unroll
            for (int ni = 0; ni < 8; ni++) {
                oacc[ni][0] *= scA; oacc[ni][1] *= scA;
                oacc[ni][2] *= scB; oacc[ni][3] *= scB;
            }
            // ---- O += P * V^T  (P repacked, pipelined V frags) ----
#pragma unroll
            for (int j = 0; j < 4; j++) {
                uint32_t Ph[4], Pl[4];
                pack_hl(sacc[2 * j][0],     sacc[2 * j][1],     Ph[0], Pl[0]);
                pack_hl(sacc[2 * j][2],     sacc[2 * j][3],     Ph[1], Pl[1]);
                pack_hl(sacc[2 * j + 1][0], sacc[2 * j + 1][1], Ph[2], Pl[2]);
                pack_hl(sacc[2 * j + 1][2], sacc[2 * j + 1][3], Ph[3], Pl[3]);
                uint32_t vfh[2][4], vfl[2][4];
                {
                    int off = lrow * ASROW + j * 16 + lcol;    // p = 0
                    ldsm_x4(vfh[0], smem_u32(sVh + off));
                    ldsm_x4(vfl[0], smem_u32(sVl + off));
                }
#pragma unroll
                for (int p = 0; p < 4; p++) {
                    const int cur = p & 1, nxt = cur ^ 1;
                    if (p < 3) {
                        int off = ((p + 1) * 16 + lrow) * ASROW + j * 16 + lcol;
                        ldsm_x4(vfh[nxt], smem_u32(sVh + off));
                        ldsm_x4(vfl[nxt], smem_u32(sVl + off));
                    }
#pragma unroll
                    for (int qq = 0; qq < 2; qq++) {
                        int ni = 2 * p + qq;
                        mma_bf16(oacc[ni], Ph, vfh[cur][qq], vfh[cur][qq + 2]);
                        mma_bf16(oacc[ni], Ph, vfl[cur][qq], vfl[cur][qq + 2]);
                        mma_bf16(oacc[ni], Pl, vfh[cur][qq], vfh[cur][qq + 2]);
                    }
                }
            }
        }
        __syncthreads();   // all warps done with stage st before it is refilled
    }

    // ---- normalize + store bf16 hi/lo to [m][1024] ----
    float iA = 1.f / lA, iB = 1.f / lB;
    int sA = q0 + wid * 16 + rA;
    size_t rowA_off = ((size_t)b * SEQ + sA) * D_MODEL + h * 64;
    size_t rowB_off = rowA_off + (size_t)8 * D_MODEL;
#pragma unroll
    for (int ni = 0; ni < 8; ni++) {
        int n = ni * 8 + tig2;
        store_pair(Ohg, Olg, rowA_off + n, oacc[ni][0] * iA, oacc[ni][1] * iA);
        store_pair(Ohg, Olg, rowB_off + n, oacc[ni][2] * iB, oacc[ni][3] * iB);
    }
}

// =================================================================
// launch
// =================================================================
extern "C" void kernel_launch(void* const* d_in, const int* in_sizes, int n_in,
                              void* d_out, int out_size) {
    const float* x  = (const float*)d_in[0];
    const float* wq = (const float*)d_in[1];
    const float* wk = (const float*)d_in[2];
    const float* wv = (const float*)d_in[3];
    const float* wo = (const float*)d_in[4];
    float* out = (float*)d_out;

    __nv_bfloat16 *xh, *xl, *wh, *wl, *qh, *ql, *kh, *kl, *vth, *vtl, *ah, *al;
    cudaGetSymbolAddress((void**)&xh, g_x_hi);
    cudaGetSymbolAddress((void**)&xl, g_x_lo);
    cudaGetSymbolAddress((void**)&wh, g_w_hi);
    cudaGetSymbolAddress((void**)&wl, g_w_lo);
    cudaGetSymbolAddress((void**)&qh, g_qh);
    cudaGetSymbolAddress((void**)&ql, g_ql);
    cudaGetSymbolAddress((void**)&kh, g_kh);
    cudaGetSymbolAddress((void**)&kl, g_kl);
    cudaGetSymbolAddress((void**)&vth, g_vth);
    cudaGetSymbolAddress((void**)&vtl, g_vtl);
    cudaGetSymbolAddress((void**)&ah, g_ah);
    cudaGetSymbolAddress((void**)&al, g_al);

    cudaFuncSetAttribute(qkv_gemm,
                         cudaFuncAttributeMaxDynamicSharedMemorySize, GEMM_SMEM);
    cudaFuncSetAttribute(o_gemm,
                         cudaFuncAttributeMaxDynamicSharedMemorySize, GEMM_SMEM);
    cudaFuncSetAttribute(attn_kernel,
                         cudaFuncAttributeMaxDynamicSharedMemorySize, ATTN_SMEM);

    // one fused split for x + all 4 weights
    split_all<<<(XF4 + 4 * WF4 + 255) / 256, 256>>>(x, wq, wk, wv, wo, xh, xl, wh, wl);

    // fused Q/K/V projections (z = 0,1,2)
    dim3 g_qkv(8, 32, 3);
    qkv_gemm<<<g_qkv, 256, GEMM_SMEM>>>(xh, xl, wh, wl, qh, ql, kh, kl, vth, vtl);

    // attention -> bf16 hi/lo [m][1024]
    dim3 g_at(SEQ / 128, BATCH * N_HEADS);    // (16, 32), LPT order inside
    attn_kernel<<<g_at, 256, ATTN_SMEM>>>(qh, ql, kh, kl, vth, vtl, ah, al);

    // output projection -> fp32 out
    dim3 g_o(8, 32);
    o_gemm<<<g_o, 256, GEMM_SMEM>>>(ah, al, wh + 3 * (size_t)WN, wl + 3 * (size_t)WN, out);
}

// round 11
// speedup vs baseline: 1.4282x; 1.4282x over previous
#include <cuda_runtime.h>
#include <cuda_fp16.h>
#include <cstdint>
#include <math.h>

#define D_MODEL 1024
#define N_HEADS 16
#define HEAD_DIM 64
#define BATCH 2
#define SEQ 2048
#define M_TOT (BATCH * SEQ)   // 4096
#define WN (D_MODEL * D_MODEL)

// ---------------- scratch (no allocations allowed) ----------------
__device__ __half g_x_hi[M_TOT * D_MODEL];
__device__ __half g_x_lo[M_TOT * D_MODEL];
__device__ __half g_w_hi[4 * WN];   // wq,wk,wv,wo
__device__ __half g_w_lo[4 * WN];
__device__ __half g_qh[M_TOT * D_MODEL];                        // [b,h,s,d] hi only
__device__ __half g_kh[M_TOT * D_MODEL], g_kl[M_TOT * D_MODEL]; // [b,h,s,d]
__device__ __half g_vth[M_TOT * D_MODEL], g_vtl[M_TOT * D_MODEL]; // [h*64+d][b*2048+s]
__device__ __half g_ah[M_TOT * D_MODEL];                        // [m][1024] hi only

// =================== portable PTX helpers ===================
__device__ __forceinline__ uint32_t smem_u32(const void* p) {
    uint32_t a;
    asm("{ .reg .u64 t; cvta.to.shared.u64 t, %1; cvt.u32.u64 %0, t; }"
        : "=r"(a) : "l"(p));
    return a;
}

__device__ __forceinline__ void ldsm_x4(uint32_t* r, uint32_t addr) {
    asm volatile("ldmatrix.sync.aligned.m8n8.x4.shared.b16 {%0,%1,%2,%3}, [%4];"
                 : "=r"(r[0]), "=r"(r[1]), "=r"(r[2]), "=r"(r[3]) : "r"(addr));
}

// D += A * B  (m16n8k16, fp16 in, fp32 acc)
__device__ __forceinline__ void mma_f16(float* d, const uint32_t* a,
                                        uint32_t b0, uint32_t b1) {
    asm volatile(
        "mma.sync.aligned.m16n8k16.row.col.f32.f16.f16.f32 "
        "{%0,%1,%2,%3}, {%4,%5,%6,%7}, {%8,%9}, {%0,%1,%2,%3};"
        : "+f"(d[0]), "+f"(d[1]), "+f"(d[2]), "+f"(d[3])
        : "r"(a[0]), "r"(a[1]), "r"(a[2]), "r"(a[3]), "r"(b0), "r"(b1));
}

__device__ __forceinline__ void cp16(void* dst_smem, const void* src) {
    uint32_t d = smem_u32(dst_smem);
    asm volatile("cp.async.cg.shared.global [%0], [%1], 16;" :: "r"(d), "l"(src) : "memory");
}
#define CP_COMMIT() asm volatile("cp.async.commit_group;" ::: "memory")

__device__ __forceinline__ uint32_t pack_h(float v0, float v1) {
    __half2 h = __floats2half2_rn(v0, v1);
    return *(uint32_t*)&h;
}
__device__ __forceinline__ void store_hl(__half* Oh, __half* Ol, size_t off,
                                         float v0, float v1) {
    __half2 h = __floats2half2_rn(v0, v1);
    __half2 l = __floats2half2_rn(v0 - __half2float(__low2half(h)),
                                  v1 - __half2float(__high2half(h)));
    *(__half2*)(Oh + off) = h;
    *(__half2*)(Ol + off) = l;
}
__device__ __forceinline__ void store_h(__half* Oh, size_t off, float v0, float v1) {
    *(__half2*)(Oh + off) = __floats2half2_rn(v0, v1);
}

// =================================================================
// fused split: x (1M float4) + 4 weights (256K float4 each) -> fp16 hi/lo
// =================================================================
#define XF4 (M_TOT * D_MODEL / 4)   // 1048576
#define WF4 (WN / 4)                // 262144

__global__ __launch_bounds__(256)
void split_all(const float* __restrict__ x, const float* __restrict__ wq,
               const float* __restrict__ wk, const float* __restrict__ wv,
               const float* __restrict__ wo,
               __half* __restrict__ xh, __half* __restrict__ xl,
               __half* __restrict__ wh, __half* __restrict__ wl) {
    int i = blockIdx.x * 256 + threadIdx.x;
    const float* src;
    __half *hi, *lo;
    int off;
    if (i < XF4) {
        src = x; hi = xh; lo = xl; off = i;
    } else {
        int j = i - XF4;
        int w = j >> 18;            // /WF4
        off = j & (WF4 - 1);
        src = (w == 0) ? wq : (w == 1) ? wk : (w == 2) ? wv : wo;
        hi = wh + (size_t)w * WN;
        lo = wl + (size_t)w * WN;
    }
    float4 v = ((const float4*)src)[off];
    __half2 h0 = __floats2half2_rn(v.x, v.y);
    __half2 h1 = __floats2half2_rn(v.z, v.w);
    __half2 l0 = __floats2half2_rn(v.x - __half2float(__low2half(h0)),
                                   v.y - __half2float(__high2half(h0)));
    __half2 l1 = __floats2half2_rn(v.z - __half2float(__low2half(h1)),
                                   v.w - __half2float(__high2half(h1)));
    ((uint2*)hi)[off] = make_uint2(*(uint32_t*)&h0, *(uint32_t*)&h1);
    ((uint2*)lo)[off] = make_uint2(*(uint32_t*)&l0, *(uint32_t*)&l1);
}

// =================================================================
// GEMM body: C tile = A[.,1024](hi) @ (W_hi + W_lo)[.,1024]^T
// fp16 x2 compensated, cp.async 2-stage. 8 warps (2m x 4n), BK=32.
// MODE 0: fp32 row-major C (ldc)
// MODE 1: fp16 hi+lo -> [b,h,s,d] head layout   (K)
// MODE 2: fp16 hi only -> [b,h,s,d] head layout (Q)
// MODE 3: fp16 hi+lo row-major (ldc)            (V-transposed)
// =================================================================
#define SROW 40                        // smem row stride in halves
#define STAGE_B (128 * SROW * 2)       // 10240 B per tile
#define GSTAGE (3 * STAGE_B)           // 30720 B per stage (Ah, Bh, Bl)
#define GEMM_SMEM (2 * GSTAGE)         // 61440 B

__device__ __forceinline__ void gemm_body(
    char* gsm,
    const __half* __restrict__ Ah_g,
    const __half* __restrict__ Whi, const __half* __restrict__ Wlo,
    float* __restrict__ C, __half* __restrict__ Oh, __half* __restrict__ Ol,
    int ldc, int MODE, int bm, int bn) {
    const int tid = threadIdx.x;
    const int wid = tid >> 5, lane = tid & 31;
    const int wmr = wid >> 2, wnr = wid & 3;

    float acc[4][4][4];
#pragma unroll
    for (int i = 0; i < 4; i++)
#pragma unroll
        for (int j = 0; j < 4; j++)
#pragma unroll
            for (int r = 0; r < 4; r++) acc[i][j][r] = 0.f;

    const int lrow = lane & 15, lcol = (lane >> 4) * 8;

    auto fill = [&](int st, int k0) {
        char* base = gsm + st * GSTAGE;
#pragma unroll
        for (int i = 0; i < 2; i++) {
            int c = tid + i * 256;
            int row = c >> 2, kc = (c & 3) * 8;
            int so = (row * SROW + kc) * 2;
            size_t ga = (size_t)(bm + row) * 1024 + k0 + kc;
            size_t gb = (size_t)(bn + row) * 1024 + k0 + kc;
            cp16(base + so, Ah_g + ga);
            cp16(base + STAGE_B + so, Whi + gb);
            cp16(base + 2 * STAGE_B + so, Wlo + gb);
        }
        CP_COMMIT();
    };

    fill(0, 0);
    for (int ch = 0; ch < 32; ch++) {
        if (ch + 1 < 32) {
            fill((ch + 1) & 1, (ch + 1) * 32);
            asm volatile("cp.async.wait_group 1;" ::: "memory");
        } else {
            asm volatile("cp.async.wait_group 0;" ::: "memory");
        }
        __syncthreads();
        char* base = gsm + (ch & 1) * GSTAGE;
        __half* sAh = (__half*)base;
        __half* sBh = (__half*)(base + STAGE_B);
        __half* sBl = (__half*)(base + 2 * STAGE_B);

#pragma unroll
        for (int ks = 0; ks < 32; ks += 16) {
            uint32_t bh[2][4], bl[2][4];
#pragma unroll
            for (int p = 0; p < 2; p++) {
                int off = (wnr * 32 + p * 16 + lrow) * SROW + ks + lcol;
                ldsm_x4(bh[p], smem_u32(sBh + off));
                ldsm_x4(bl[p], smem_u32(sBl + off));
            }
            uint32_t ah[2][4];
            {
                int off = (wmr * 64 + lrow) * SROW + ks + lcol;
                ldsm_x4(ah[0], smem_u32(sAh + off));
            }
#pragma unroll
            for (int mi = 0; mi < 4; mi++) {
                const int cur = mi & 1, nxt = cur ^ 1;
                if (mi < 3) {
                    int off = (wmr * 64 + (mi + 1) * 16 + lrow) * SROW + ks + lcol;
                    ldsm_x4(ah[nxt], smem_u32(sAh + off));
                }
#pragma unroll
                for (int ni = 0; ni < 4; ni++) {
                    int p = ni >> 1, q = ni & 1;
                    mma_f16(acc[mi][ni], ah[cur], bh[p][q], bh[p][q + 2]);
                    mma_f16(acc[mi][ni], ah[cur], bl[p][q], bl[p][q + 2]);
                }
            }
        }
        __syncthreads();
    }

    // ---- epilogue ----
    const int r_in = lane >> 2, c_in = (lane & 3) * 2;
#pragma unroll
    for (int mi = 0; mi < 4; mi++) {
#pragma unroll
        for (int ni = 0; ni < 4; ni++) {
            int m0 = bm + wmr * 64 + mi * 16 + r_in;
            int n  = bn + wnr * 32 + ni * 8 + c_in;
            float v0 = acc[mi][ni][0], v1 = acc[mi][ni][1];
            float v2 = acc[mi][ni][2], v3 = acc[mi][ni][3];
            if (MODE == 0) {
                *(float2*)(C + (size_t)m0 * ldc + n) = make_float2(v0, v1);
                *(float2*)(C + (size_t)(m0 + 8) * ldc + n) = make_float2(v2, v3);
            } else if (MODE == 3) {
                store_hl(Oh, Ol, (size_t)m0 * ldc + n, v0, v1);
                store_hl(Oh, Ol, (size_t)(m0 + 8) * ldc + n, v2, v3);
            } else {  // MODE 1 / 2: [b,h,s,d]
                int h = n >> 6, d = n & 63;
#pragma unroll
                for (int rr = 0; rr < 2; rr++) {
                    int m = m0 + rr * 8;
                    int b = m >> 11, s = m & 2047;
                    size_t off = ((size_t)((b * N_HEADS + h) * SEQ + s)) * HEAD_DIM + d;
                    if (MODE == 1)
                        store_hl(Oh, Ol, off, acc[mi][ni][2 * rr], acc[mi][ni][2 * rr + 1]);
                    else
                        store_h(Oh, off, acc[mi][ni][2 * rr], acc[mi][ni][2 * rr + 1]);
                }
            }
        }
    }
}

// fused Q/K/V projections: z=0 -> Q (hi only), z=1 -> K, z=2 -> V-transposed
__global__ __launch_bounds__(256, 2)
void qkv_gemm(const __half* __restrict__ xh, const __half* __restrict__ xl,
              const __half* __restrict__ wh, const __half* __restrict__ wl,
              __half* __restrict__ qh,
              __half* __restrict__ kh, __half* __restrict__ kl,
              __half* __restrict__ vth, __half* __restrict__ vtl) {
    extern __shared__ char gsm[];
    const int z = blockIdx.z;
    if (z == 0) {
        gemm_body(gsm, xh, wh, wl, nullptr, qh, nullptr, 0, 2,
                  blockIdx.y * 128, blockIdx.x * 128);
    } else if (z == 1) {
        gemm_body(gsm, xh, wh + WN, wl + WN, nullptr, kh, kl, 0, 1,
                  blockIdx.y * 128, blockIdx.x * 128);
    } else {
        // V transposed: C' = wv(hi) @ (x_hi + x_lo)^T -> [channel][token]
        gemm_body(gsm, wh + 2 * (size_t)WN, xh, xl,
                  nullptr, vth, vtl, M_TOT, 3,
                  blockIdx.x * 128, blockIdx.y * 128);
    }
}

// output projection: fp32 row-major
__global__ __launch_bounds__(256, 2)
void o_gemm(const __half* __restrict__ ah,
            const __half* __restrict__ wh, const __half* __restrict__ wl,
            float* __restrict__ out) {
    extern __shared__ char gsm[];
    gemm_body(gsm, ah, wh, wl, out, nullptr, nullptr, D_MODEL, 0,
              blockIdx.y * 128, blockIdx.x * 128);
}

// =================================================================
// Flash attention on mma.sync, fp16 x2 compensated, causal.
// CTA: 128 q rows x full head. 8 warps, warp = 16 q rows. Key tiles 64.
// cp.async 2-stage double-buffered K/V hi/lo tiles. Q-hi frags in regs.
// S = Qh (Kh + Kl)^T ; O += P (Vh + Vl)^T with P single fp16.
// LPT: longest CTAs (high qt) launch first.
// =================================================================
#define ASROW 72
#define ABUF_B (64 * ASROW * 2)        // 9216 B per tile buffer
#define ASTAGE (4 * ABUF_B)            // 36864 B per stage
#define ATTN_SMEM (2 * ASTAGE)         // 73728 B

__global__ __launch_bounds__(256, 2)
void attn_kernel(const __half* __restrict__ Qh,
                 const __half* __restrict__ Kh, const __half* __restrict__ Kl,
                 const __half* __restrict__ Vh, const __half* __restrict__ Vl,
                 __half* __restrict__ Ohg) {
    extern __shared__ char asm_raw[];
    auto buf = [&](int st, int w) -> __half* {
        return (__half*)(asm_raw + st * ASTAGE + w * ABUF_B);
    };

    const int tid = threadIdx.x, wid = tid >> 5, lane = tid & 31;
    const int qt = (int)gridDim.x - 1 - (int)blockIdx.x;   // LPT: long CTAs first
    const int bh = blockIdx.y;
    const int b = bh >> 4, h = bh & 15;
    const int q0 = qt * 128;
    const size_t qkbase = (size_t)bh * SEQ * HEAD_DIM;
    const size_t vbase = (size_t)(h * 64) * 4096 + (size_t)b * 2048;

    const int lrow = lane & 15, lcol = (lane >> 4) * 8;
    const int rA = lane >> 2;
    const int tig2 = (lane & 3) * 2;

    // ---- stage Q-hi into fragments via stage-0 scratch ----
#pragma unroll
    for (int i = 0; i < 4; i++) {
        int c = tid + i * 256;
        int row = c >> 3, cc = (c & 7) * 8;
        __half* dst = buf(0, row < 64 ? 0 : 1) + (row & 63) * ASROW + cc;
        *(uint4*)dst = *(const uint4*)(Qh + qkbase + (size_t)(q0 + row) * 64 + cc);
    }
    __syncthreads();
    uint32_t qfh[4][4];
    {
        int qr = wid * 16 + lrow;
        const __half* bq = buf(0, qr < 64 ? 0 : 1);
        int qrl = qr & 63;
#pragma unroll
        for (int ks = 0; ks < 4; ks++)
            ldsm_x4(qfh[ks], smem_u32(bq + qrl * ASROW + ks * 16 + lcol));
    }
    __syncthreads();   // scratch free before fillKV overwrites it

    auto fillKV = [&](int st, int k0) {
#pragma unroll
        for (int i = 0; i < 2; i++) {
            int c = tid + i * 256;
            int row = c >> 3, cc = (c & 7) * 8;
            int so = row * ASROW + cc;
            cp16(buf(st, 0) + so, Kh + qkbase + (size_t)(k0 + row) * 64 + cc);
            cp16(buf(st, 1) + so, Kl + qkbase + (size_t)(k0 + row) * 64 + cc);
            cp16(buf(st, 2) + so, Vh + vbase + (size_t)row * 4096 + k0 + cc);
            cp16(buf(st, 3) + so, Vl + vbase + (size_t)row * 4096 + k0 + cc);
        }
        CP_COMMIT();
    };

    float oacc[8][4];
#pragma unroll
    for (int i = 0; i < 8; i++)
#pragma unroll
        for (int j = 0; j < 4; j++) oacc[i][j] = 0.f;
    float mMA = -1e30f, mMB = -1e30f, lA = 0.f, lB = 0.f;

    const int nt = 2 * qt + 2;
    fillKV(0, 0);
    for (int jt = 0; jt < nt; jt++) {
        const int k0 = jt * 64;
        if (jt + 1 < nt) {
            fillKV((jt + 1) & 1, (jt + 1) * 64);
            asm volatile("cp.async.wait_group 1;" ::: "memory");
        } else {
            asm volatile("cp.async.wait_group 0;" ::: "memory");
        }
        __syncthreads();
        const int st = jt & 1;
        __half* sKh = buf(st, 0);
        __half* sKl = buf(st, 1);
        __half* sVh = buf(st, 2);
        __half* sVl = buf(st, 3);

        const int wrow0 = q0 + wid * 16;
        if (k0 <= wrow0 + 15) {
            // ---- scores S = Qh (Kh + Kl)^T, pipelined K frags ----
            float sacc[8][4];
#pragma unroll
            for (int i = 0; i < 8; i++)
#pragma unroll
                for (int j = 0; j < 4; j++) sacc[i][j] = 0.f;
#pragma unroll
            for (int ks = 0; ks < 4; ks++) {
                uint32_t kfh[2][4], kfl[2][4];
                {
                    int off = lrow * ASROW + ks * 16 + lcol;   // p = 0
                    ldsm_x4(kfh[0], smem_u32(sKh + off));
                    ldsm_x4(kfl[0], smem_u32(sKl + off));
                }
#pragma unroll
                for (int p = 0; p < 4; p++) {
                    const int cur = p & 1, nxt = cur ^ 1;
                    if (p < 3) {
                        int off = ((p + 1) * 16 + lrow) * ASROW + ks * 16 + lcol;
                        ldsm_x4(kfh[nxt], smem_u32(sKh + off));
                        ldsm_x4(kfl[nxt], smem_u32(sKl + off));
                    }
#pragma unroll
                    for (int qq = 0; qq < 2; qq++) {
                        int ni = 2 * p + qq;
                        mma_f16(sacc[ni], qfh[ks], kfh[cur][qq], kfh[cur][qq + 2]);
                        mma_f16(sacc[ni], qfh[ks], kfl[cur][qq], kfl[cur][qq + 2]);
                    }
                }
            }
            // ---- scale + causal mask ----
            const bool band = (k0 + 63 > wrow0);
            const int rowAg = wrow0 + rA, rowBg = rowAg + 8;
#pragma unroll
            for (int ni = 0; ni < 8; ni++) {
                int colb = k0 + ni * 8 + tig2;
#pragma unroll
                for (int e = 0; e < 4; e++) {
                    float s = sacc[ni][e] * 0.125f;
                    if (band) {
                        int col = colb + (e & 1);
                        int row = (e < 2) ? rowAg : rowBg;
                        if (col > row) s = -1e30f;
                    }
                    sacc[ni][e] = s;
                }
            }
            // ---- online softmax ----
            float mxA = -1e30f, mxB = -1e30f;
#pragma unroll
            for (int ni = 0; ni < 8; ni++) {
                mxA = fmaxf(mxA, fmaxf(sacc[ni][0], sacc[ni][1]));
                mxB = fmaxf(mxB, fmaxf(sacc[ni][2], sacc[ni][3]));
            }
            mxA = fmaxf(mxA, __shfl_xor_sync(0xffffffffu, mxA, 1));
            mxA = fmaxf(mxA, __shfl_xor_sync(0xffffffffu, mxA, 2));
            mxB = fmaxf(mxB, __shfl_xor_sync(0xffffffffu, mxB, 1));
            mxB = fmaxf(mxB, __shfl_xor_sync(0xffffffffu, mxB, 2));
            float mnA = fmaxf(mMA, mxA), mnB = fmaxf(mMB, mxB);
            float scA = __expf(mMA - mnA), scB = __expf(mMB - mnB);
            mMA = mnA; mMB = mnB;
            float suA = 0.f, suB = 0.f;
#pragma unroll
            for (int ni = 0; ni < 8; ni++) {
                sacc[ni][0] = __expf(sacc[ni][0] - mnA); suA += sacc[ni][0];
                sacc[ni][1] = __expf(sacc[ni][1] - mnA); suA += sacc[ni][1];
                sacc[ni][2] = __expf(sacc[ni][2] - mnB); suB += sacc[ni][2];
                sacc[ni][3] = __expf(sacc[ni][3] - mnB); suB += sacc[ni][3];
            }
            suA += __shfl_xor_sync(0xffffffffu, suA, 1);
            suA += __shfl_xor_sync(0xffffffffu, suA, 2);
            suB += __shfl_xor_sync(0xffffffffu, suB, 1);
            suB += __shfl_xor_sync(0xffffffffu, suB, 2);
            lA = lA * scA + suA;
            lB = lB * scB + suB;
#pragma unroll
            for (int ni = 0; ni < 8; ni++) {
                oacc[ni][0] *= scA; oacc[ni][1] *= scA;
                oacc[ni][2] *= scB; oacc[ni][3] *= scB;
            }
            // ---- O += P (Vh + Vl)^T, P single fp16, pipelined V frags ----
#pragma unroll
            for (int j = 0; j < 4; j++) {
                uint32_t Ph[4];
                Ph[0] = pack_h(sacc[2 * j][0],     sacc[2 * j][1]);
                Ph[1] = pack_h(sacc[2 * j][2],     sacc[2 * j][3]);
                Ph[2] = pack_h(sacc[2 * j + 1][0], sacc[2 * j + 1][1]);
                Ph[3] = pack_h(sacc[2 * j + 1][2], sacc[2 * j + 1][3]);
                uint32_t vfh[2][4], vfl[2][4];
                {
                    int off = lrow * ASROW + j * 16 + lcol;    // p = 0
                    ldsm_x4(vfh[0], smem_u32(sVh + off));
                    ldsm_x4(vfl[0], smem_u32(sVl + off));
                }
#pragma unroll
                for (int p = 0; p < 4; p++) {
                    const int cur = p & 1, nxt = cur ^ 1;
                    if (p < 3) {
                        int off = ((p + 1) * 16 + lrow) * ASROW + j * 16 + lcol;
                        ldsm_x4(vfh[nxt], smem_u32(sVh + off));
                        ldsm_x4(vfl[nxt], smem_u32(sVl + off));
                    }
#pragma unroll
                    for (int qq = 0; qq < 2; qq++) {
                        int ni = 2 * p + qq;
                        mma_f16(oacc[ni], Ph, vfh[cur][qq], vfh[cur][qq + 2]);
                        mma_f16(oacc[ni], Ph, vfl[cur][qq], vfl[cur][qq + 2]);
                    }
                }
            }
        }
        __syncthreads();   // all warps done with stage st before it is refilled
    }

    // ---- normalize + store fp16 hi to [m][1024] ----
    float iA = 1.f / lA, iB = 1.f / lB;
    int sA = q0 + wid * 16 + rA;
    size_t rowA_off = ((size_t)b * SEQ + sA) * D_MODEL + h * 64;
    size_t rowB_off = rowA_off + (size_t)8 * D_MODEL;
#pragma unroll
    for (int ni = 0; ni < 8; ni++) {
        int n = ni * 8 + tig2;
        store_h(Ohg, rowA_off + n, oacc[ni][0] * iA, oacc[ni][1] * iA);
        store_h(Ohg, rowB_off + n, oacc[ni][2] * iB, oacc[ni][3] * iB);
    }
}

// =================================================================
// launch
// =================================================================
extern "C" void kernel_launch(void* const* d_in, const int* in_sizes, int n_in,
                              void* d_out, int out_size) {
    const float* x  = (const float*)d_in[0];
    const float* wq = (const float*)d_in[1];
    const float* wk = (const float*)d_in[2];
    const float* wv = (const float*)d_in[3];
    const float* wo = (const float*)d_in[4];
    float* out = (float*)d_out;

    __half *xh, *xl, *wh, *wl, *qh, *kh, *kl, *vth, *vtl, *ah;
    cudaGetSymbolAddress((void**)&xh, g_x_hi);
    cudaGetSymbolAddress((void**)&xl, g_x_lo);
    cudaGetSymbolAddress((void**)&wh, g_w_hi);
    cudaGetSymbolAddress((void**)&wl, g_w_lo);
    cudaGetSymbolAddress((void**)&qh, g_qh);
    cudaGetSymbolAddress((void**)&kh, g_kh);
    cudaGetSymbolAddress((void**)&kl, g_kl);
    cudaGetSymbolAddress((void**)&vth, g_vth);
    cudaGetSymbolAddress((void**)&vtl, g_vtl);
    cudaGetSymbolAddress((void**)&ah, g_ah);

    cudaFuncSetAttribute(qkv_gemm,
                         cudaFuncAttributeMaxDynamicSharedMemorySize, GEMM_SMEM);
    cudaFuncSetAttribute(o_gemm,
                         cudaFuncAttributeMaxDynamicSharedMemorySize, GEMM_SMEM);
    cudaFuncSetAttribute(attn_kernel,
                         cudaFuncAttributeMaxDynamicSharedMemorySize, ATTN_SMEM);

    // one fused split for x + all 4 weights
    split_all<<<(XF4 + 4 * WF4 + 255) / 256, 256>>>(x, wq, wk, wv, wo, xh, xl, wh, wl);

    // fused Q/K/V projections (z = 0,1,2)
    dim3 g_qkv(8, 32, 3);
    qkv_gemm<<<g_qkv, 256, GEMM_SMEM>>>(xh, xl, wh, wl, qh, kh, kl, vth, vtl);

    // attention -> fp16 hi [m][1024]
    dim3 g_at(SEQ / 128, BATCH * N_HEADS);    // (16, 32), LPT order inside
    attn_kernel<<<g_at, 256, ATTN_SMEM>>>(qh, kh, kl, vth, vtl, ah);

    // output projection -> fp32 out
    dim3 g_o(8, 32);
    o_gemm<<<g_o, 256, GEMM_SMEM>>>(ah, wh + 3 * (size_t)WN, wl + 3 * (size_t)WN, out);
}

// round 12
// speedup vs baseline: 1.4613x; 1.0232x over previous
#include <cuda_runtime.h>
#include <cuda_fp16.h>
#include <cstdint>
#include <math.h>

#define D_MODEL 1024
#define N_HEADS 16
#define HEAD_DIM 64
#define BATCH 2
#define SEQ 2048
#define M_TOT (BATCH * SEQ)   // 4096
#define WN (D_MODEL * D_MODEL)

// ---------------- scratch (no allocations allowed) ----------------
__device__ __half g_x_hi[M_TOT * D_MODEL];
__device__ __half g_x_lo[M_TOT * D_MODEL];
__device__ __half g_w_hi[4 * WN];   // wq,wk,wv,wo
__device__ __half g_w_lo[4 * WN];
__device__ __half g_qh[M_TOT * D_MODEL];                        // [b,h,s,d] hi only
__device__ __half g_kh[M_TOT * D_MODEL], g_kl[M_TOT * D_MODEL]; // [b,h,s,d]
__device__ __half g_vth[M_TOT * D_MODEL], g_vtl[M_TOT * D_MODEL]; // [h*64+d][b*2048+s]
__device__ __half g_ah[M_TOT * D_MODEL];                        // [m][1024] hi only

// =================== portable PTX helpers ===================
__device__ __forceinline__ uint32_t smem_u32(const void* p) {
    uint32_t a;
    asm("{ .reg .u64 t; cvta.to.shared.u64 t, %1; cvt.u32.u64 %0, t; }"
        : "=r"(a) : "l"(p));
    return a;
}

__device__ __forceinline__ void ldsm_x4(uint32_t* r, uint32_t addr) {
    asm volatile("ldmatrix.sync.aligned.m8n8.x4.shared.b16 {%0,%1,%2,%3}, [%4];"
                 : "=r"(r[0]), "=r"(r[1]), "=r"(r[2]), "=r"(r[3]) : "r"(addr));
}

// D += A * B  (m16n8k16, fp16 in, fp32 acc)
__device__ __forceinline__ void mma_f16(float* d, const uint32_t* a,
                                        uint32_t b0, uint32_t b1) {
    asm volatile(
        "mma.sync.aligned.m16n8k16.row.col.f32.f16.f16.f32 "
        "{%0,%1,%2,%3}, {%4,%5,%6,%7}, {%8,%9}, {%0,%1,%2,%3};"
        : "+f"(d[0]), "+f"(d[1]), "+f"(d[2]), "+f"(d[3])
        : "r"(a[0]), "r"(a[1]), "r"(a[2]), "r"(a[3]), "r"(b0), "r"(b1));
}

__device__ __forceinline__ void cp16(void* dst_smem, const void* src) {
    uint32_t d = smem_u32(dst_smem);
    asm volatile("cp.async.cg.shared.global [%0], [%1], 16;" :: "r"(d), "l"(src) : "memory");
}
#define CP_COMMIT() asm volatile("cp.async.commit_group;" ::: "memory")

__device__ __forceinline__ uint32_t pack_h(float v0, float v1) {
    __half2 h = __floats2half2_rn(v0, v1);
    return *(uint32_t*)&h;
}
__device__ __forceinline__ void store_hl(__half* Oh, __half* Ol, size_t off,
                                         float v0, float v1) {
    __half2 h = __floats2half2_rn(v0, v1);
    __half2 l = __floats2half2_rn(v0 - __half2float(__low2half(h)),
                                  v1 - __half2float(__high2half(h)));
    *(__half2*)(Oh + off) = h;
    *(__half2*)(Ol + off) = l;
}
__device__ __forceinline__ void store_h(__half* Oh, size_t off, float v0, float v1) {
    *(__half2*)(Oh + off) = __floats2half2_rn(v0, v1);
}

// =================================================================
// fused split: x (1M float4) + 4 weights (256K float4 each) -> fp16 hi/lo
// =================================================================
#define XF4 (M_TOT * D_MODEL / 4)   // 1048576
#define WF4 (WN / 4)                // 262144

__global__ __launch_bounds__(256)
void split_all(const float* __restrict__ x, const float* __restrict__ wq,
               const float* __restrict__ wk, const float* __restrict__ wv,
               const float* __restrict__ wo,
               __half* __restrict__ xh, __half* __restrict__ xl,
               __half* __restrict__ wh, __half* __restrict__ wl) {
    int i = blockIdx.x * 256 + threadIdx.x;
    const float* src;
    __half *hi, *lo;
    int off;
    if (i < XF4) {
        src = x; hi = xh; lo = xl; off = i;
    } else {
        int j = i - XF4;
        int w = j >> 18;            // /WF4
        off = j & (WF4 - 1);
        src = (w == 0) ? wq : (w == 1) ? wk : (w == 2) ? wv : wo;
        hi = wh + (size_t)w * WN;
        lo = wl + (size_t)w * WN;
    }
    float4 v = ((const float4*)src)[off];
    __half2 h0 = __floats2half2_rn(v.x, v.y);
    __half2 h1 = __floats2half2_rn(v.z, v.w);
    __half2 l0 = __floats2half2_rn(v.x - __half2float(__low2half(h0)),
                                   v.y - __half2float(__high2half(h0)));
    __half2 l1 = __floats2half2_rn(v.z - __half2float(__low2half(h1)),
                                   v.w - __half2float(__high2half(h1)));
    ((uint2*)hi)[off] = make_uint2(*(uint32_t*)&h0, *(uint32_t*)&h1);
    ((uint2*)lo)[off] = make_uint2(*(uint32_t*)&l0, *(uint32_t*)&l1);
}

// =================================================================
// GEMM body: C tile = A[.,1024](hi) @ (W_hi + W_lo)[.,1024]^T
// fp16 x2 compensated, cp.async 2-stage, BK=64 (128 MMAs per barrier).
// MODE 0: fp32 row-major C (ldc)
// MODE 1: fp16 hi+lo -> [b,h,s,d] head layout   (K)
// MODE 2: fp16 hi only -> [b,h,s,d] head layout (Q)
// MODE 3: fp16 hi+lo row-major (ldc)            (V-transposed)
// =================================================================
#define GROW 72                        // smem row stride in halves (64 + 8 pad)
#define GTILE_B (128 * GROW * 2)       // 18432 B per tile
#define GSTAGE (3 * GTILE_B)           // 55296 B per stage (Ah, Bh, Bl)
#define GEMM_SMEM (2 * GSTAGE)         // 110592 B  (2 CTAs = 221 KB <= 228 KB)

__device__ __forceinline__ void gemm_body(
    char* gsm,
    const __half* __restrict__ Ah_g,
    const __half* __restrict__ Whi, const __half* __restrict__ Wlo,
    float* __restrict__ C, __half* __restrict__ Oh, __half* __restrict__ Ol,
    int ldc, int MODE, int bm, int bn) {
    const int tid = threadIdx.x;
    const int wid = tid >> 5, lane = tid & 31;
    const int wmr = wid >> 2, wnr = wid & 3;

    float acc[4][4][4];
#pragma unroll
    for (int i = 0; i < 4; i++)
#pragma unroll
        for (int j = 0; j < 4; j++)
#pragma unroll
            for (int r = 0; r < 4; r++) acc[i][j][r] = 0.f;

    const int lrow = lane & 15, lcol = (lane >> 4) * 8;

    // fill one 64-wide K chunk (3 tiles: Ah, Bh, Bl)
    auto fill = [&](int st, int k0) {
        char* base = gsm + st * GSTAGE;
#pragma unroll
        for (int i = 0; i < 4; i++) {
            int c = tid + i * 256;          // 0..1023 (row, 16B chunk)
            int row = c >> 3, kc = (c & 7) * 8;
            int so = (row * GROW + kc) * 2;
            size_t ga = (size_t)(bm + row) * 1024 + k0 + kc;
            size_t gb = (size_t)(bn + row) * 1024 + k0 + kc;
            cp16(base + so, Ah_g + ga);
            cp16(base + GTILE_B + so, Whi + gb);
            cp16(base + 2 * GTILE_B + so, Wlo + gb);
        }
        CP_COMMIT();
    };

    fill(0, 0);
    for (int ch = 0; ch < 16; ch++) {
        if (ch + 1 < 16) {
            fill((ch + 1) & 1, (ch + 1) * 64);
            asm volatile("cp.async.wait_group 1;" ::: "memory");
        } else {
            asm volatile("cp.async.wait_group 0;" ::: "memory");
        }
        __syncthreads();
        char* base = gsm + (ch & 1) * GSTAGE;
        __half* sAh = (__half*)base;
        __half* sBh = (__half*)(base + GTILE_B);
        __half* sBl = (__half*)(base + 2 * GTILE_B);

#pragma unroll
        for (int ks = 0; ks < 64; ks += 16) {
            uint32_t bh[2][4], bl[2][4];
#pragma unroll
            for (int p = 0; p < 2; p++) {
                int off = (wnr * 32 + p * 16 + lrow) * GROW + ks + lcol;
                ldsm_x4(bh[p], smem_u32(sBh + off));
                ldsm_x4(bl[p], smem_u32(sBl + off));
            }
            uint32_t ah[2][4];
            {
                int off = (wmr * 64 + lrow) * GROW + ks + lcol;
                ldsm_x4(ah[0], smem_u32(sAh + off));
            }
#pragma unroll
            for (int mi = 0; mi < 4; mi++) {
                const int cur = mi & 1, nxt = cur ^ 1;
                if (mi < 3) {
                    int off = (wmr * 64 + (mi + 1) * 16 + lrow) * GROW + ks + lcol;
                    ldsm_x4(ah[nxt], smem_u32(sAh + off));
                }
#pragma unroll
                for (int ni = 0; ni < 4; ni++) {
                    int p = ni >> 1, q = ni & 1;
                    mma_f16(acc[mi][ni], ah[cur], bh[p][q], bh[p][q + 2]);
                    mma_f16(acc[mi][ni], ah[cur], bl[p][q], bl[p][q + 2]);
                }
            }
        }
        __syncthreads();
    }

    // ---- epilogue ----
    const int r_in = lane >> 2, c_in = (lane & 3) * 2;
#pragma unroll
    for (int mi = 0; mi < 4; mi++) {
#pragma unroll
        for (int ni = 0; ni < 4; ni++) {
            int m0 = bm + wmr * 64 + mi * 16 + r_in;
            int n  = bn + wnr * 32 + ni * 8 + c_in;
            float v0 = acc[mi][ni][0], v1 = acc[mi][ni][1];
            float v2 = acc[mi][ni][2], v3 = acc[mi][ni][3];
            if (MODE == 0) {
                *(float2*)(C + (size_t)m0 * ldc + n) = make_float2(v0, v1);
                *(float2*)(C + (size_t)(m0 + 8) * ldc + n) = make_float2(v2, v3);
            } else if (MODE == 3) {
                store_hl(Oh, Ol, (size_t)m0 * ldc + n, v0, v1);
                store_hl(Oh, Ol, (size_t)(m0 + 8) * ldc + n, v2, v3);
            } else {  // MODE 1 / 2: [b,h,s,d]
                int h = n >> 6, d = n & 63;
#pragma unroll
                for (int rr = 0; rr < 2; rr++) {
                    int m = m0 + rr * 8;
                    int b = m >> 11, s = m & 2047;
                    size_t off = ((size_t)((b * N_HEADS + h) * SEQ + s)) * HEAD_DIM + d;
                    if (MODE == 1)
                        store_hl(Oh, Ol, off, acc[mi][ni][2 * rr], acc[mi][ni][2 * rr + 1]);
                    else
                        store_h(Oh, off, acc[mi][ni][2 * rr], acc[mi][ni][2 * rr + 1]);
                }
            }
        }
    }
}

// fused Q/K/V projections: z=0 -> Q (hi only), z=1 -> K, z=2 -> V-transposed
__global__ __launch_bounds__(256, 2)
void qkv_gemm(const __half* __restrict__ xh, const __half* __restrict__ xl,
              const __half* __restrict__ wh, const __half* __restrict__ wl,
              __half* __restrict__ qh,
              __half* __restrict__ kh, __half* __restrict__ kl,
              __half* __restrict__ vth, __half* __restrict__ vtl) {
    extern __shared__ char gsm[];
    const int z = blockIdx.z;
    if (z == 0) {
        gemm_body(gsm, xh, wh, wl, nullptr, qh, nullptr, 0, 2,
                  blockIdx.y * 128, blockIdx.x * 128);
    } else if (z == 1) {
        gemm_body(gsm, xh, wh + WN, wl + WN, nullptr, kh, kl, 0, 1,
                  blockIdx.y * 128, blockIdx.x * 128);
    } else {
        // V transposed: C' = wv(hi) @ (x_hi + x_lo)^T -> [channel][token]
        gemm_body(gsm, wh + 2 * (size_t)WN, xh, xl,
                  nullptr, vth, vtl, M_TOT, 3,
                  blockIdx.x * 128, blockIdx.y * 128);
    }
}

// output projection: fp32 row-major
__global__ __launch_bounds__(256, 2)
void o_gemm(const __half* __restrict__ ah,
            const __half* __restrict__ wh, const __half* __restrict__ wl,
            float* __restrict__ out) {
    extern __shared__ char gsm[];
    gemm_body(gsm, ah, wh, wl, out, nullptr, nullptr, D_MODEL, 0,
              blockIdx.y * 128, blockIdx.x * 128);
}

// =================================================================
// Flash attention on mma.sync, fp16 x2 compensated, causal.
// CTA: 128 q rows x full head. 8 warps, warp = 16 q rows. Key tiles 64.
// cp.async 2-stage double-buffered K/V hi/lo tiles. Q-hi frags in regs.
// S = Qh (Kh + Kl)^T ; O += P (Vh + Vl)^T with P single fp16.
// LPT: longest CTAs (high qt) launch first.
// =================================================================
#define ASROW 72
#define ABUF_B (64 * ASROW * 2)        // 9216 B per tile buffer
#define ASTAGE (4 * ABUF_B)            // 36864 B per stage
#define ATTN_SMEM (2 * ASTAGE)         // 73728 B

__global__ __launch_bounds__(256, 2)
void attn_kernel(const __half* __restrict__ Qh,
                 const __half* __restrict__ Kh, const __half* __restrict__ Kl,
                 const __half* __restrict__ Vh, const __half* __restrict__ Vl,
                 __half* __restrict__ Ohg) {
    extern __shared__ char asm_raw[];
    auto buf = [&](int st, int w) -> __half* {
        return (__half*)(asm_raw + st * ASTAGE + w * ABUF_B);
    };

    const int tid = threadIdx.x, wid = tid >> 5, lane = tid & 31;
    const int qt = (int)gridDim.x - 1 - (int)blockIdx.x;   // LPT: long CTAs first
    const int bh = blockIdx.y;
    const int b = bh >> 4, h = bh & 15;
    const int q0 = qt * 128;
    const size_t qkbase = (size_t)bh * SEQ * HEAD_DIM;
    const size_t vbase = (size_t)(h * 64) * 4096 + (size_t)b * 2048;

    const int lrow = lane & 15, lcol = (lane >> 4) * 8;
    const int rA = lane >> 2;
    const int tig2 = (lane & 3) * 2;

    // ---- stage Q-hi into fragments via stage-0 scratch ----
#pragma unroll
    for (int i = 0; i < 4; i++) {
        int c = tid + i * 256;
        int row = c >> 3, cc = (c & 7) * 8;
        __half* dst = buf(0, row < 64 ? 0 : 1) + (row & 63) * ASROW + cc;
        *(uint4*)dst = *(const uint4*)(Qh + qkbase + (size_t)(q0 + row) * 64 + cc);
    }
    __syncthreads();
    uint32_t qfh[4][4];
    {
        int qr = wid * 16 + lrow;
        const __half* bq = buf(0, qr < 64 ? 0 : 1);
        int qrl = qr & 63;
#pragma unroll
        for (int ks = 0; ks < 4; ks++)
            ldsm_x4(qfh[ks], smem_u32(bq + qrl * ASROW + ks * 16 + lcol));
    }
    __syncthreads();   // scratch free before fillKV overwrites it

    auto fillKV = [&](int st, int k0) {
#pragma unroll
        for (int i = 0; i < 2; i++) {
            int c = tid + i * 256;
            int row = c >> 3, cc = (c & 7) * 8;
            int so = row * ASROW + cc;
            cp16(buf(st, 0) + so, Kh + qkbase + (size_t)(k0 + row) * 64 + cc);
            cp16(buf(st, 1) + so, Kl + qkbase + (size_t)(k0 + row) * 64 + cc);
            cp16(buf(st, 2) + so, Vh + vbase + (size_t)row * 4096 + k0 + cc);
            cp16(buf(st, 3) + so, Vl + vbase + (size_t)row * 4096 + k0 + cc);
        }
        CP_COMMIT();
    };

    float oacc[8][4];
#pragma unroll
    for (int i = 0; i < 8; i++)
#pragma unroll
        for (int j = 0; j < 4; j++) oacc[i][j] = 0.f;
    float mMA = -1e30f, mMB = -1e30f, lA = 0.f, lB = 0.f;

    const int nt = 2 * qt + 2;
    fillKV(0, 0);
    for (int jt = 0; jt < nt; jt++) {
        const int k0 = jt * 64;
        if (jt + 1 < nt) {
            fillKV((jt + 1) & 1, (jt + 1) * 64);
            asm volatile("cp.async.wait_group 1;" ::: "memory");
        } else {
            asm volatile("cp.async.wait_group 0;" ::: "memory");
        }
        __syncthreads();
        const int st = jt & 1;
        __half* sKh = buf(st, 0);
        __half* sKl = buf(st, 1);
        __half* sVh = buf(st, 2);
        __half* sVl = buf(st, 3);

        const int wrow0 = q0 + wid * 16;
        if (k0 <= wrow0 + 15) {
            // ---- scores S = Qh (Kh + Kl)^T, pipelined K frags ----
            float sacc[8][4];
#pragma unroll
            for (int i = 0; i < 8; i++)
#pragma unroll
                for (int j = 0; j < 4; j++) sacc[i][j] = 0.f;
#pragma unroll
            for (int ks = 0; ks < 4; ks++) {
                uint32_t kfh[2][4], kfl[2][4];
                {
                    int off = lrow * ASROW + ks * 16 + lcol;   // p = 0
                    ldsm_x4(kfh[0], smem_u32(sKh + off));
                    ldsm_x4(kfl[0], smem_u32(sKl + off));
                }
#pragma unroll
                for (int p = 0; p < 4; p++) {
                    const int cur = p & 1, nxt = cur ^ 1;
                    if (p < 3) {
                        int off = ((p + 1) * 16 + lrow) * ASROW + ks * 16 + lcol;
                        ldsm_x4(kfh[nxt], smem_u32(sKh + off));
                        ldsm_x4(kfl[nxt], smem_u32(sKl + off));
                    }
#pragma unroll
                    for (int qq = 0; qq < 2; qq++) {
                        int ni = 2 * p + qq;
                        mma_f16(sacc[ni], qfh[ks], kfh[cur][qq], kfh[cur][qq + 2]);
                        mma_f16(sacc[ni], qfh[ks], kfl[cur][qq], kfl[cur][qq + 2]);
                    }
                }
            }
            // ---- scale + causal mask ----
            const bool band = (k0 + 63 > wrow0);
            const int rowAg = wrow0 + rA, rowBg = rowAg + 8;
#pragma unroll
            for (int ni = 0; ni < 8; ni++) {
                int colb = k0 + ni * 8 + tig2;
#pragma unroll
                for (int e = 0; e < 4; e++) {
                    float s = sacc[ni][e] * 0.125f;
                    if (band) {
                        int col = colb + (e & 1);
                        int row = (e < 2) ? rowAg : rowBg;
                        if (col > row) s = -1e30f;
                    }
                    sacc[ni][e] = s;
                }
            }
            // ---- online softmax ----
            float mxA = -1e30f, mxB = -1e30f;
#pragma unroll
            for (int ni = 0; ni < 8; ni++) {
                mxA = fmaxf(mxA, fmaxf(sacc[ni][0], sacc[ni][1]));
                mxB = fmaxf(mxB, fmaxf(sacc[ni][2], sacc[ni][3]));
            }
            mxA = fmaxf(mxA, __shfl_xor_sync(0xffffffffu, mxA, 1));
            mxA = fmaxf(mxA, __shfl_xor_sync(0xffffffffu, mxA, 2));
            mxB = fmaxf(mxB, __shfl_xor_sync(0xffffffffu, mxB, 1));
            mxB = fmaxf(mxB, __shfl_xor_sync(0xffffffffu, mxB, 2));
            float mnA = fmaxf(mMA, mxA), mnB = fmaxf(mMB, mxB);
            float scA = __expf(mMA - mnA), scB = __expf(mMB - mnB);
            mMA = mnA; mMB = mnB;
            float suA = 0.f, suB = 0.f;
#pragma unroll
            for (int ni = 0; ni < 8; ni++) {
                sacc[ni][0] = __expf(sacc[ni][0] - mnA); suA += sacc[ni][0];
                sacc[ni][1] = __expf(sacc[ni][1] - mnA); suA += sacc[ni][1];
                sacc[ni][2] = __expf(sacc[ni][2] - mnB); suB += sacc[ni][2];
                sacc[ni][3] = __expf(sacc[ni][3] - mnB); suB += sacc[ni][3];
            }
            suA += __shfl_xor_sync(0xffffffffu, suA, 1);
            suA += __shfl_xor_sync(0xffffffffu, suA, 2);
            suB += __shfl_xor_sync(0xffffffffu, suB, 1);
            suB += __shfl_xor_sync(0xffffffffu, suB, 2);
            lA = lA * scA + suA;
            lB = lB * scB + suB;
#pragma unroll
            for (int ni = 0; ni < 8; ni++) {
                oacc[ni][0] *= scA; oacc[ni][1] *= scA;
                oacc[ni][2] *= scB; oacc[ni][3] *= scB;
            }
            // ---- O += P (Vh + Vl)^T, P single fp16, pipelined V frags ----
#pragma unroll
            for (int j = 0; j < 4; j++) {
                uint32_t Ph[4];
                Ph[0] = pack_h(sacc[2 * j][0],     sacc[2 * j][1]);
                Ph[1] = pack_h(sacc[2 * j][2],     sacc[2 * j][3]);
                Ph[2] = pack_h(sacc[2 * j + 1][0], sacc[2 * j + 1][1]);
                Ph[3] = pack_h(sacc[2 * j + 1][2], sacc[2 * j + 1][3]);
                uint32_t vfh[2][4], vfl[2][4];
                {
                    int off = lrow * ASROW + j * 16 + lcol;    // p = 0
                    ldsm_x4(vfh[0], smem_u32(sVh + off));
                    ldsm_x4(vfl[0], smem_u32(sVl + off));
                }
#pragma unroll
                for (int p = 0; p < 4; p++) {
                    const int cur = p & 1, nxt = cur ^ 1;
                    if (p < 3) {
                        int off = ((p + 1) * 16 + lrow) * ASROW + j * 16 + lcol;
                        ldsm_x4(vfh[nxt], smem_u32(sVh + off));
                        ldsm_x4(vfl[nxt], smem_u32(sVl + off));
                    }
#pragma unroll
                    for (int qq = 0; qq < 2; qq++) {
                        int ni = 2 * p + qq;
                        mma_f16(oacc[ni], Ph, vfh[cur][qq], vfh[cur][qq + 2]);
                        mma_f16(oacc[ni], Ph, vfl[cur][qq], vfl[cur][qq + 2]);
                    }
                }
            }
        }
        __syncthreads();   // all warps done with stage st before it is refilled
    }

    // ---- normalize + store fp16 hi to [m][1024] ----
    float iA = 1.f / lA, iB = 1.f / lB;
    int sA = q0 + wid * 16 + rA;
    size_t rowA_off = ((size_t)b * SEQ + sA) * D_MODEL + h * 64;
    size_t rowB_off = rowA_off + (size_t)8 * D_MODEL;
#pragma unroll
    for (int ni = 0; ni < 8; ni++) {
        int n = ni * 8 + tig2;
        store_h(Ohg, rowA_off + n, oacc[ni][0] * iA, oacc[ni][1] * iA);
        store_h(Ohg, rowB_off + n, oacc[ni][2] * iB, oacc[ni][3] * iB);
    }
}

// =================================================================
// launch
// =================================================================
extern "C" void kernel_launch(void* const* d_in, const int* in_sizes, int n_in,
                              void* d_out, int out_size) {
    const float* x  = (const float*)d_in[0];
    const float* wq = (const float*)d_in[1];
    const float* wk = (const float*)d_in[2];
    const float* wv = (const float*)d_in[3];
    const float* wo = (const float*)d_in[4];
    float* out = (float*)d_out;

    __half *xh, *xl, *wh, *wl, *qh, *kh, *kl, *vth, *vtl, *ah;
    cudaGetSymbolAddress((void**)&xh, g_x_hi);
    cudaGetSymbolAddress((void**)&xl, g_x_lo);
    cudaGetSymbolAddress((void**)&wh, g_w_hi);
    cudaGetSymbolAddress((void**)&wl, g_w_lo);
    cudaGetSymbolAddress((void**)&qh, g_qh);
    cudaGetSymbolAddress((void**)&kh, g_kh);
    cudaGetSymbolAddress((void**)&kl, g_kl);
    cudaGetSymbolAddress((void**)&vth, g_vth);
    cudaGetSymbolAddress((void**)&vtl, g_vtl);
    cudaGetSymbolAddress((void**)&ah, g_ah);

    cudaFuncSetAttribute(qkv_gemm,
                         cudaFuncAttributeMaxDynamicSharedMemorySize, GEMM_SMEM);
    cudaFuncSetAttribute(o_gemm,
                         cudaFuncAttributeMaxDynamicSharedMemorySize, GEMM_SMEM);
    cudaFuncSetAttribute(attn_kernel,
                         cudaFuncAttributeMaxDynamicSharedMemorySize, ATTN_SMEM);

    // one fused split for x + all 4 weights
    split_all<<<(XF4 + 4 * WF4 + 255) / 256, 256>>>(x, wq, wk, wv, wo, xh, xl, wh, wl);

    // fused Q/K/V projections (z = 0,1,2)
    dim3 g_qkv(8, 32, 3);
    qkv_gemm<<<g_qkv, 256, GEMM_SMEM>>>(xh, xl, wh, wl, qh, kh, kl, vth, vtl);

    // attention -> fp16 hi [m][1024]
    dim3 g_at(SEQ / 128, BATCH * N_HEADS);    // (16, 32), LPT order inside
    attn_kernel<<<g_at, 256, ATTN_SMEM>>>(qh, kh, kl, vth, vtl, ah);

    // output projection -> fp32 out
    dim3 g_o(8, 32);
    o_gemm<<<g_o, 256, GEMM_SMEM>>>(ah, wh + 3 * (size_t)WN, wl + 3 * (size_t)WN, out);
}

// round 13
// speedup vs baseline: 1.9127x; 1.3089x over previous
#include <cuda_runtime.h>
#include <cuda_fp16.h>
#include <cstdint>
#include <math.h>

#define D_MODEL 1024
#define N_HEADS 16
#define HEAD_DIM 64
#define BATCH 2
#define SEQ 2048
#define M_TOT (BATCH * SEQ)   // 4096
#define WN (D_MODEL * D_MODEL)

// ---------------- scratch (no allocations allowed) ----------------
__device__ __half g_x_hi[M_TOT * D_MODEL];
__device__ __half g_w_hi[4 * WN];   // wq,wk,wv,wo
__device__ __half g_w_lo[4 * WN];   // only wk, wo slots used
__device__ __half g_qh[M_TOT * D_MODEL];                        // [b,h,s,d] hi only
__device__ __half g_kh[M_TOT * D_MODEL], g_kl[M_TOT * D_MODEL]; // [b,h,s,d]
__device__ __half g_vth[M_TOT * D_MODEL];                       // [h*64+d][b*2048+s] hi only
__device__ __half g_ah[M_TOT * D_MODEL];                        // [m][1024] hi only

// =================== portable PTX helpers ===================
__device__ __forceinline__ uint32_t smem_u32(const void* p) {
    uint32_t a;
    asm("{ .reg .u64 t; cvta.to.shared.u64 t, %1; cvt.u32.u64 %0, t; }"
        : "=r"(a) : "l"(p));
    return a;
}

__device__ __forceinline__ void ldsm_x4(uint32_t* r, uint32_t addr) {
    asm volatile("ldmatrix.sync.aligned.m8n8.x4.shared.b16 {%0,%1,%2,%3}, [%4];"
                 : "=r"(r[0]), "=r"(r[1]), "=r"(r[2]), "=r"(r[3]) : "r"(addr));
}

// D += A * B  (m16n8k16, fp16 in, fp32 acc)
__device__ __forceinline__ void mma_f16(float* d, const uint32_t* a,
                                        uint32_t b0, uint32_t b1) {
    asm volatile(
        "mma.sync.aligned.m16n8k16.row.col.f32.f16.f16.f32 "
        "{%0,%1,%2,%3}, {%4,%5,%6,%7}, {%8,%9}, {%0,%1,%2,%3};"
        : "+f"(d[0]), "+f"(d[1]), "+f"(d[2]), "+f"(d[3])
        : "r"(a[0]), "r"(a[1]), "r"(a[2]), "r"(a[3]), "r"(b0), "r"(b1));
}

__device__ __forceinline__ void cp16(void* dst_smem, const void* src) {
    uint32_t d = smem_u32(dst_smem);
    asm volatile("cp.async.cg.shared.global [%0], [%1], 16;" :: "r"(d), "l"(src) : "memory");
}
#define CP_COMMIT() asm volatile("cp.async.commit_group;" ::: "memory")

__device__ __forceinline__ uint32_t pack_h(float v0, float v1) {
    __half2 h = __floats2half2_rn(v0, v1);
    return *(uint32_t*)&h;
}
__device__ __forceinline__ void store_hl(__half* Oh, __half* Ol, size_t off,
                                         float v0, float v1) {
    __half2 h = __floats2half2_rn(v0, v1);
    __half2 l = __floats2half2_rn(v0 - __half2float(__low2half(h)),
                                  v1 - __half2float(__high2half(h)));
    *(__half2*)(Oh + off) = h;
    *(__half2*)(Ol + off) = l;
}
__device__ __forceinline__ void store_h(__half* Oh, size_t off, float v0, float v1) {
    *(__half2*)(Oh + off) = __floats2half2_rn(v0, v1);
}

// =================================================================
// fused split: x -> fp16 hi; weights -> fp16 hi (+ lo for wk, wo)
// =================================================================
#define XF4 (M_TOT * D_MODEL / 4)   // 1048576
#define WF4 (WN / 4)                // 262144

__global__ __launch_bounds__(256)
void split_all(const float* __restrict__ x, const float* __restrict__ wq,
               const float* __restrict__ wk, const float* __restrict__ wv,
               const float* __restrict__ wo,
               __half* __restrict__ xh,
               __half* __restrict__ wh, __half* __restrict__ wl) {
    int i = blockIdx.x * 256 + threadIdx.x;
    const float* src;
    __half *hi, *lo = nullptr;
    int off;
    if (i < XF4) {
        src = x; hi = xh; off = i;
    } else {
        int j = i - XF4;
        int w = j >> 18;            // /WF4
        off = j & (WF4 - 1);
        src = (w == 0) ? wq : (w == 1) ? wk : (w == 2) ? wv : wo;
        hi = wh + (size_t)w * WN;
        if (w == 1 || w == 3) lo = wl + (size_t)w * WN;   // only K, O weights need lo
    }
    float4 v = ((const float4*)src)[off];
    __half2 h0 = __floats2half2_rn(v.x, v.y);
    __half2 h1 = __floats2half2_rn(v.z, v.w);
    ((uint2*)hi)[off] = make_uint2(*(uint32_t*)&h0, *(uint32_t*)&h1);
    if (lo) {
        __half2 l0 = __floats2half2_rn(v.x - __half2float(__low2half(h0)),
                                       v.y - __half2float(__high2half(h0)));
        __half2 l1 = __floats2half2_rn(v.z - __half2float(__low2half(h1)),
                                       v.w - __half2float(__high2half(h1)));
        ((uint2*)lo)[off] = make_uint2(*(uint32_t*)&l0, *(uint32_t*)&l1);
    }
}

// =================================================================
// GEMM body: C tile = A[.,1024](hi) @ (W_hi [+ W_lo])[.,1024]^T
// cp.async 2-stage, BK=64. HAS_LO selects 2-term compensation.
// MODE 0: fp32 row-major C (ldc)
// MODE 1: fp16 hi+lo -> [b,h,s,d] head layout   (K)
// MODE 2: fp16 hi only -> [b,h,s,d] head layout (Q)
// MODE 4: fp16 hi only row-major (ldc)          (V-transposed)
// =================================================================
#define GROW 72                        // smem row stride in halves (64 + 8 pad)
#define GTILE_B (128 * GROW * 2)       // 18432 B per tile
#define GEMM_SMEM (2 * 3 * GTILE_B)    // 110592 B worst case (2 CTAs <= 228 KB)

template <bool HAS_LO, int MODE>
__device__ __forceinline__ void gemm_body(
    char* gsm,
    const __half* __restrict__ Ah_g,
    const __half* __restrict__ Whi, const __half* __restrict__ Wlo,
    float* __restrict__ C, __half* __restrict__ Oh, __half* __restrict__ Ol,
    int ldc, int bm, int bn) {
    constexpr int NT = HAS_LO ? 3 : 2;         // tiles per stage
    constexpr int GSTAGE_T = NT * GTILE_B;
    const int tid = threadIdx.x;
    const int wid = tid >> 5, lane = tid & 31;
    const int wmr = wid >> 2, wnr = wid & 3;

    float acc[4][4][4];
#pragma unroll
    for (int i = 0; i < 4; i++)
#pragma unroll
        for (int j = 0; j < 4; j++)
#pragma unroll
            for (int r = 0; r < 4; r++) acc[i][j][r] = 0.f;

    const int lrow = lane & 15, lcol = (lane >> 4) * 8;

    auto fill = [&](int st, int k0) {
        char* base = gsm + st * GSTAGE_T;
#pragma unroll
        for (int i = 0; i < 4; i++) {
            int c = tid + i * 256;          // 0..1023 (row, 16B chunk)
            int row = c >> 3, kc = (c & 7) * 8;
            int so = (row * GROW + kc) * 2;
            size_t ga = (size_t)(bm + row) * 1024 + k0 + kc;
            size_t gb = (size_t)(bn + row) * 1024 + k0 + kc;
            cp16(base + so, Ah_g + ga);
            cp16(base + GTILE_B + so, Whi + gb);
            if (HAS_LO) cp16(base + 2 * GTILE_B + so, Wlo + gb);
        }
        CP_COMMIT();
    };

    fill(0, 0);
    for (int ch = 0; ch < 16; ch++) {
        if (ch + 1 < 16) {
            fill((ch + 1) & 1, (ch + 1) * 64);
            asm volatile("cp.async.wait_group 1;" ::: "memory");
        } else {
            asm volatile("cp.async.wait_group 0;" ::: "memory");
        }
        __syncthreads();
        char* base = gsm + (ch & 1) * GSTAGE_T;
        __half* sAh = (__half*)base;
        __half* sBh = (__half*)(base + GTILE_B);
        __half* sBl = (__half*)(base + 2 * GTILE_B);

#pragma unroll
        for (int ks = 0; ks < 64; ks += 16) {
            uint32_t bh[2][4], bl[2][4];
#pragma unroll
            for (int p = 0; p < 2; p++) {
                int off = (wnr * 32 + p * 16 + lrow) * GROW + ks + lcol;
                ldsm_x4(bh[p], smem_u32(sBh + off));
                if (HAS_LO) ldsm_x4(bl[p], smem_u32(sBl + off));
            }
            uint32_t ah[2][4];
            {
                int off = (wmr * 64 + lrow) * GROW + ks + lcol;
                ldsm_x4(ah[0], smem_u32(sAh + off));
            }
#pragma unroll
            for (int mi = 0; mi < 4; mi++) {
                const int cur = mi & 1, nxt = cur ^ 1;
                if (mi < 3) {
                    int off = (wmr * 64 + (mi + 1) * 16 + lrow) * GROW + ks + lcol;
                    ldsm_x4(ah[nxt], smem_u32(sAh + off));
                }
#pragma unroll
                for (int ni = 0; ni < 4; ni++) {
                    int p = ni >> 1, q = ni & 1;
                    mma_f16(acc[mi][ni], ah[cur], bh[p][q], bh[p][q + 2]);
                    if (HAS_LO) mma_f16(acc[mi][ni], ah[cur], bl[p][q], bl[p][q + 2]);
                }
            }
        }
        __syncthreads();
    }

    // ---- epilogue ----
    const int r_in = lane >> 2, c_in = (lane & 3) * 2;
#pragma unroll
    for (int mi = 0; mi < 4; mi++) {
#pragma unroll
        for (int ni = 0; ni < 4; ni++) {
            int m0 = bm + wmr * 64 + mi * 16 + r_in;
            int n  = bn + wnr * 32 + ni * 8 + c_in;
            float v0 = acc[mi][ni][0], v1 = acc[mi][ni][1];
            float v2 = acc[mi][ni][2], v3 = acc[mi][ni][3];
            if (MODE == 0) {
                *(float2*)(C + (size_t)m0 * ldc + n) = make_float2(v0, v1);
                *(float2*)(C + (size_t)(m0 + 8) * ldc + n) = make_float2(v2, v3);
            } else if (MODE == 4) {
                store_h(Oh, (size_t)m0 * ldc + n, v0, v1);
                store_h(Oh, (size_t)(m0 + 8) * ldc + n, v2, v3);
            } else {  // MODE 1 / 2: [b,h,s,d]
                int h = n >> 6, d = n & 63;
#pragma unroll
                for (int rr = 0; rr < 2; rr++) {
                    int m = m0 + rr * 8;
                    int b = m >> 11, s = m & 2047;
                    size_t off = ((size_t)((b * N_HEADS + h) * SEQ + s)) * HEAD_DIM + d;
                    if (MODE == 1)
                        store_hl(Oh, Ol, off, acc[mi][ni][2 * rr], acc[mi][ni][2 * rr + 1]);
                    else
                        store_h(Oh, off, acc[mi][ni][2 * rr], acc[mi][ni][2 * rr + 1]);
                }
            }
        }
    }
}

// fused Q/K/V projections: z=0 -> Q (1-term), z=1 -> K (2-term), z=2 -> Vt (1-term)
__global__ __launch_bounds__(256, 2)
void qkv_gemm(const __half* __restrict__ xh,
              const __half* __restrict__ wh, const __half* __restrict__ wl,
              __half* __restrict__ qh,
              __half* __restrict__ kh, __half* __restrict__ kl,
              __half* __restrict__ vth) {
    extern __shared__ char gsm[];
    const int z = blockIdx.z;
    if (z == 0) {
        gemm_body<false, 2>(gsm, xh, wh, nullptr, nullptr, qh, nullptr, 0,
                            blockIdx.y * 128, blockIdx.x * 128);
    } else if (z == 1) {
        gemm_body<true, 1>(gsm, xh, wh + WN, wl + WN, nullptr, kh, kl, 0,
                           blockIdx.y * 128, blockIdx.x * 128);
    } else {
        // V transposed: C' = wv(hi) @ x(hi)^T -> [channel][token], hi only
        gemm_body<false, 4>(gsm, wh + 2 * (size_t)WN, xh, nullptr,
                            nullptr, vth, nullptr, M_TOT,
                            blockIdx.x * 128, blockIdx.y * 128);
    }
}

// output projection: fp32 row-major, compensated (2-term)
__global__ __launch_bounds__(256, 2)
void o_gemm(const __half* __restrict__ ah,
            const __half* __restrict__ wh, const __half* __restrict__ wl,
            float* __restrict__ out) {
    extern __shared__ char gsm[];
    gemm_body<true, 0>(gsm, ah, wh, wl, out, nullptr, nullptr, D_MODEL,
                       blockIdx.y * 128, blockIdx.x * 128);
}

// =================================================================
// Flash attention on mma.sync, causal.
// S = Qh (Kh + Kl)^T (compensated); O += P * Vh^T (1-term fp16).
// CTA: 128 q rows x full head. 8 warps, warp = 16 q rows. Key tiles 64.
// cp.async 2-stage double-buffered Kh/Kl/Vh tiles. LPT scheduling.
// =================================================================
#define ASROW 72
#define ABUF_B (64 * ASROW * 2)        // 9216 B per tile buffer
#define ASTAGE (3 * ABUF_B)            // 27648 B per stage (Kh, Kl, Vh)
#define ATTN_SMEM (2 * ASTAGE)         // 55296 B

__global__ __launch_bounds__(256, 2)
void attn_kernel(const __half* __restrict__ Qh,
                 const __half* __restrict__ Kh, const __half* __restrict__ Kl,
                 const __half* __restrict__ Vh,
                 __half* __restrict__ Ohg) {
    extern __shared__ char asm_raw[];
    auto buf = [&](int st, int w) -> __half* {
        return (__half*)(asm_raw + st * ASTAGE + w * ABUF_B);
    };

    const int tid = threadIdx.x, wid = tid >> 5, lane = tid & 31;
    const int qt = (int)gridDim.x - 1 - (int)blockIdx.x;   // LPT: long CTAs first
    const int bh = blockIdx.y;
    const int b = bh >> 4, h = bh & 15;
    const int q0 = qt * 128;
    const size_t qkbase = (size_t)bh * SEQ * HEAD_DIM;
    const size_t vbase = (size_t)(h * 64) * 4096 + (size_t)b * 2048;

    const int lrow = lane & 15, lcol = (lane >> 4) * 8;
    const int rA = lane >> 2;
    const int tig2 = (lane & 3) * 2;

    // ---- stage Q-hi into fragments via stage-0 scratch ----
#pragma unroll
    for (int i = 0; i < 4; i++) {
        int c = tid + i * 256;
        int row = c >> 3, cc = (c & 7) * 8;
        __half* dst = buf(0, row < 64 ? 0 : 1) + (row & 63) * ASROW + cc;
        *(uint4*)dst = *(const uint4*)(Qh + qkbase + (size_t)(q0 + row) * 64 + cc);
    }
    __syncthreads();
    uint32_t qfh[4][4];
    {
        int qr = wid * 16 + lrow;
        const __half* bq = buf(0, qr < 64 ? 0 : 1);
        int qrl = qr & 63;
#pragma unroll
        for (int ks = 0; ks < 4; ks++)
            ldsm_x4(qfh[ks], smem_u32(bq + qrl * ASROW + ks * 16 + lcol));
    }
    __syncthreads();   // scratch free before fillKV overwrites it

    auto fillKV = [&](int st, int k0) {
#pragma unroll
        for (int i = 0; i < 2; i++) {
            int c = tid + i * 256;
            int row = c >> 3, cc = (c & 7) * 8;
            int so = row * ASROW + cc;
            cp16(buf(st, 0) + so, Kh + qkbase + (size_t)(k0 + row) * 64 + cc);
            cp16(buf(st, 1) + so, Kl + qkbase + (size_t)(k0 + row) * 64 + cc);
            cp16(buf(st, 2) + so, Vh + vbase + (size_t)row * 4096 + k0 + cc);
        }
        CP_COMMIT();
    };

    float oacc[8][4];
#pragma unroll
    for (int i = 0; i < 8; i++)
#pragma unroll
        for (int j = 0; j < 4; j++) oacc[i][j] = 0.f;
    float mMA = -1e30f, mMB = -1e30f, lA = 0.f, lB = 0.f;

    const int nt = 2 * qt + 2;
    fillKV(0, 0);
    for (int jt = 0; jt < nt; jt++) {
        const int k0 = jt * 64;
        if (jt + 1 < nt) {
            fillKV((jt + 1) & 1, (jt + 1) * 64);
            asm volatile("cp.async.wait_group 1;" ::: "memory");
        } else {
            asm volatile("cp.async.wait_group 0;" ::: "memory");
        }
        __syncthreads();
        const int st = jt & 1;
        __half* sKh = buf(st, 0);
        __half* sKl = buf(st, 1);
        __half* sVh = buf(st, 2);

        const int wrow0 = q0 + wid * 16;
        if (k0 <= wrow0 + 15) {
            // ---- scores S = Qh (Kh + Kl)^T, pipelined K frags ----
            float sacc[8][4];
#pragma unroll
            for (int i = 0; i < 8; i++)
#pragma unroll
                for (int j = 0; j < 4; j++) sacc[i][j] = 0.f;
#pragma unroll
            for (int ks = 0; ks < 4; ks++) {
                uint32_t kfh[2][4], kfl[2][4];
                {
                    int off = lrow * ASROW + ks * 16 + lcol;   // p = 0
                    ldsm_x4(kfh[0], smem_u32(sKh + off));
                    ldsm_x4(kfl[0], smem_u32(sKl + off));
                }
#pragma unroll
                for (int p = 0; p < 4; p++) {
                    const int cur = p & 1, nxt = cur ^ 1;
                    if (p < 3) {
                        int off = ((p + 1) * 16 + lrow) * ASROW + ks * 16 + lcol;
                        ldsm_x4(kfh[nxt], smem_u32(sKh + off));
                        ldsm_x4(kfl[nxt], smem_u32(sKl + off));
                    }
#pragma unroll
                    for (int qq = 0; qq < 2; qq++) {
                        int ni = 2 * p + qq;
                        mma_f16(sacc[ni], qfh[ks], kfh[cur][qq], kfh[cur][qq + 2]);
                        mma_f16(sacc[ni], qfh[ks], kfl[cur][qq], kfl[cur][qq + 2]);
                    }
                }
            }
            // ---- scale + causal mask ----
            const bool band = (k0 + 63 > wrow0);
            const int rowAg = wrow0 + rA, rowBg = rowAg + 8;
#pragma unroll
            for (int ni = 0; ni < 8; ni++) {
                int colb = k0 + ni * 8 + tig2;
#pragma unroll
                for (int e = 0; e < 4; e++) {
                    float s = sacc[ni][e] * 0.125f;
                    if (band) {
                        int col = colb + (e & 1);
                        int row = (e < 2) ? rowAg : rowBg;
                        if (col > row) s = -1e30f;
                    }
                    sacc[ni][e] = s;
                }
            }
            // ---- online softmax ----
            float mxA = -1e30f, mxB = -1e30f;
#pragma unroll
            for (int ni = 0; ni < 8; ni++) {
                mxA = fmaxf(mxA, fmaxf(sacc[ni][0], sacc[ni][1]));
                mxB = fmaxf(mxB, fmaxf(sacc[ni][2], sacc[ni][3]));
            }
            mxA = fmaxf(mxA, __shfl_xor_sync(0xffffffffu, mxA, 1));
            mxA = fmaxf(mxA, __shfl_xor_sync(0xffffffffu, mxA, 2));
            mxB = fmaxf(mxB, __shfl_xor_sync(0xffffffffu, mxB, 1));
            mxB = fmaxf(mxB, __shfl_xor_sync(0xffffffffu, mxB, 2));
            float mnA = fmaxf(mMA, mxA), mnB = fmaxf(mMB, mxB);
            float scA = __expf(mMA - mnA), scB = __expf(mMB - mnB);
            mMA = mnA; mMB = mnB;
            float suA = 0.f, suB = 0.f;
#pragma unroll
            for (int ni = 0; ni < 8; ni++) {
                sacc[ni][0] = __expf(sacc[ni][0] - mnA); suA += sacc[ni][0];
                sacc[ni][1] = __expf(sacc[ni][1] - mnA); suA += sacc[ni][1];
                sacc[ni][2] = __expf(sacc[ni][2] - mnB); suB += sacc[ni][2];
                sacc[ni][3] = __expf(sacc[ni][3] - mnB); suB += sacc[ni][3];
            }
            suA += __shfl_xor_sync(0xffffffffu, suA, 1);
            suA += __shfl_xor_sync(0xffffffffu, suA, 2);
            suB += __shfl_xor_sync(0xffffffffu, suB, 1);
            suB += __shfl_xor_sync(0xffffffffu, suB, 2);
            lA = lA * scA + suA;
            lB = lB * scB + suB;
#pragma unroll
            for (int ni = 0; ni < 8; ni++) {
                oacc[ni][0] *= scA; oacc[ni][1] *= scA;
                oacc[ni][2] *= scB; oacc[ni][3] *= scB;
            }
            // ---- O += P * Vh^T, single term, pipelined V frags ----
#pragma unroll
            for (int j = 0; j < 4; j++) {
                uint32_t Ph[4];
                Ph[0] = pack_h(sacc[2 * j][0],     sacc[2 * j][1]);
                Ph[1] = pack_h(sacc[2 * j][2],     sacc[2 * j][3]);
                Ph[2] = pack_h(sacc[2 * j + 1][0], sacc[2 * j + 1][1]);
                Ph[3] = pack_h(sacc[2 * j + 1][2], sacc[2 * j + 1][3]);
                uint32_t vfh[2][4];
                {
                    int off = lrow * ASROW + j * 16 + lcol;    // p = 0
                    ldsm_x4(vfh[0], smem_u32(sVh + off));
                }
#pragma unroll
                for (int p = 0; p < 4; p++) {
                    const int cur = p & 1, nxt = cur ^ 1;
                    if (p < 3) {
                        int off = ((p + 1) * 16 + lrow) * ASROW + j * 16 + lcol;
                        ldsm_x4(vfh[nxt], smem_u32(sVh + off));
                    }
#pragma unroll
                    for (int qq = 0; qq < 2; qq++) {
                        int ni = 2 * p + qq;
                        mma_f16(oacc[ni], Ph, vfh[cur][qq], vfh[cur][qq + 2]);
                    }
                }
            }
        }
        __syncthreads();   // all warps done with stage st before it is refilled
    }

    // ---- normalize + store fp16 hi to [m][1024] ----
    float iA = 1.f / lA, iB = 1.f / lB;
    int sA = q0 + wid * 16 + rA;
    size_t rowA_off = ((size_t)b * SEQ + sA) * D_MODEL + h * 64;
    size_t rowB_off = rowA_off + (size_t)8 * D_MODEL;
#pragma unroll
    for (int ni = 0; ni < 8; ni++) {
        int n = ni * 8 + tig2;
        store_h(Ohg, rowA_off + n, oacc[ni][0] * iA, oacc[ni][1] * iA);
        store_h(Ohg, rowB_off + n, oacc[ni][2] * iB, oacc[ni][3] * iB);
    }
}

// =================================================================
// launch
// =================================================================
extern "C" void kernel_launch(void* const* d_in, const int* in_sizes, int n_in,
                              void* d_out, int out_size) {
    const float* x  = (const float*)d_in[0];
    const float* wq = (const float*)d_in[1];
    const float* wk = (const float*)d_in[2];
    const float* wv = (const float*)d_in[3];
    const float* wo = (const float*)d_in[4];
    float* out = (float*)d_out;

    __half *xh, *wh, *wl, *qh, *kh, *kl, *vth, *ah;
    cudaGetSymbolAddress((void**)&xh, g_x_hi);
    cudaGetSymbolAddress((void**)&wh, g_w_hi);
    cudaGetSymbolAddress((void**)&wl, g_w_lo);
    cudaGetSymbolAddress((void**)&qh, g_qh);
    cudaGetSymbolAddress((void**)&kh, g_kh);
    cudaGetSymbolAddress((void**)&kl, g_kl);
    cudaGetSymbolAddress((void**)&vth, g_vth);
    cudaGetSymbolAddress((void**)&ah, g_ah);

    cudaFuncSetAttribute(qkv_gemm,
                         cudaFuncAttributeMaxDynamicSharedMemorySize, GEMM_SMEM);
    cudaFuncSetAttribute(o_gemm,
                         cudaFuncAttributeMaxDynamicSharedMemorySize, GEMM_SMEM);
    cudaFuncSetAttribute(attn_kernel,
                         cudaFuncAttributeMaxDynamicSharedMemorySize, ATTN_SMEM);

    // one fused split for x + all 4 weights
    split_all<<<(XF4 + 4 * WF4 + 255) / 256, 256>>>(x, wq, wk, wv, wo, xh, wh, wl);

    // fused Q/K/V projections (z = 0,1,2)
    dim3 g_qkv(8, 32, 3);
    qkv_gemm<<<g_qkv, 256, GEMM_SMEM>>>(xh, wh, wl, qh, kh, kl, vth);

    // attention -> fp16 hi [m][1024]
    dim3 g_at(SEQ / 128, BATCH * N_HEADS);    // (16, 32), LPT order inside
    attn_kernel<<<g_at, 256, ATTN_SMEM>>>(qh, kh, kl, vth, ah);

    // output projection -> fp32 out (compensated)
    dim3 g_o(8, 32);
    o_gemm<<<g_o, 256, GEMM_SMEM>>>(ah, wh + 3 * (size_t)WN, wl + 3 * (size_t)WN, out);
}

// round 14
// speedup vs baseline: 2.4650x; 1.2887x over previous
#include <cuda_runtime.h>
#include <cuda_fp16.h>
#include <cstdint>
#include <math.h>

#define D_MODEL 1024
#define N_HEADS 16
#define HEAD_DIM 64
#define BATCH 2
#define SEQ 2048
#define M_TOT (BATCH * SEQ)   // 4096
#define WN (D_MODEL * D_MODEL)

// ---------------- scratch (no allocations allowed) ----------------
__device__ __half g_x_hi[M_TOT * D_MODEL];
__device__ __half g_w_hi[4 * WN];   // wq,wk,wv,wo
__device__ __half g_qh[M_TOT * D_MODEL];    // [b,h,s,d]
__device__ __half g_kh[M_TOT * D_MODEL];    // [b,h,s,d]
__device__ __half g_vth[M_TOT * D_MODEL];   // [h*64+d][b*2048+s]
__device__ __half g_ah[M_TOT * D_MODEL];    // [m][1024]

// =================== portable PTX helpers ===================
__device__ __forceinline__ uint32_t smem_u32(const void* p) {
    uint32_t a;
    asm("{ .reg .u64 t; cvta.to.shared.u64 t, %1; cvt.u32.u64 %0, t; }"
        : "=r"(a) : "l"(p));
    return a;
}

__device__ __forceinline__ void ldsm_x4(uint32_t* r, uint32_t addr) {
    asm volatile("ldmatrix.sync.aligned.m8n8.x4.shared.b16 {%0,%1,%2,%3}, [%4];"
                 : "=r"(r[0]), "=r"(r[1]), "=r"(r[2]), "=r"(r[3]) : "r"(addr));
}

// D += A * B  (m16n8k16, fp16 in, fp32 acc)
__device__ __forceinline__ void mma_f16(float* d, const uint32_t* a,
                                        uint32_t b0, uint32_t b1) {
    asm volatile(
        "mma.sync.aligned.m16n8k16.row.col.f32.f16.f16.f32 "
        "{%0,%1,%2,%3}, {%4,%5,%6,%7}, {%8,%9}, {%0,%1,%2,%3};"
        : "+f"(d[0]), "+f"(d[1]), "+f"(d[2]), "+f"(d[3])
        : "r"(a[0]), "r"(a[1]), "r"(a[2]), "r"(a[3]), "r"(b0), "r"(b1));
}

__device__ __forceinline__ void cp16(void* dst_smem, const void* src) {
    uint32_t d = smem_u32(dst_smem);
    asm volatile("cp.async.cg.shared.global [%0], [%1], 16;" :: "r"(d), "l"(src) : "memory");
}
#define CP_COMMIT() asm volatile("cp.async.commit_group;" ::: "memory")

__device__ __forceinline__ uint32_t pack_h(float v0, float v1) {
    __half2 h = __floats2half2_rn(v0, v1);
    return *(uint32_t*)&h;
}
__device__ __forceinline__ void store_h(__half* Oh, size_t off, float v0, float v1) {
    *(__half2*)(Oh + off) = __floats2half2_rn(v0, v1);
}

// =================================================================
// fused split: x + 4 weights -> fp16 (hi only)
// =================================================================
#define XF4 (M_TOT * D_MODEL / 4)   // 1048576
#define WF4 (WN / 4)                // 262144

__global__ __launch_bounds__(256)
void split_all(const float* __restrict__ x, const float* __restrict__ wq,
               const float* __restrict__ wk, const float* __restrict__ wv,
               const float* __restrict__ wo,
               __half* __restrict__ xh, __half* __restrict__ wh) {
    int i = blockIdx.x * 256 + threadIdx.x;
    const float* src;
    __half* hi;
    int off;
    if (i < XF4) {
        src = x; hi = xh; off = i;
    } else {
        int j = i - XF4;
        int w = j >> 18;            // /WF4
        off = j & (WF4 - 1);
        src = (w == 0) ? wq : (w == 1) ? wk : (w == 2) ? wv : wo;
        hi = wh + (size_t)w * WN;
    }
    float4 v = ((const float4*)src)[off];
    __half2 h0 = __floats2half2_rn(v.x, v.y);
    __half2 h1 = __floats2half2_rn(v.z, v.w);
    ((uint2*)hi)[off] = make_uint2(*(uint32_t*)&h0, *(uint32_t*)&h1);
}

// =================================================================
// GEMM body: C tile = A[.,1024] @ W[.,1024]^T, plain fp16, fp32 acc.
// cp.async 2-stage, BK=64, 128x128 tile, 8 warps (2m x 4n).
// MODE 0: fp32 row-major C (ldc)
// MODE 2: fp16 -> [b,h,s,d] head layout (Q, K)
// MODE 4: fp16 row-major (ldc)          (V-transposed)
// =================================================================
#define GROW 72                        // smem row stride in halves (64 + 8 pad)
#define GTILE_B (128 * GROW * 2)       // 18432 B per tile
#define GSTAGE (2 * GTILE_B)           // 36864 B per stage (A, B)
#define GEMM_SMEM (2 * GSTAGE)         // 73728 B

template <int MODE>
__device__ __forceinline__ void gemm_body(
    char* gsm,
    const __half* __restrict__ Ah_g, const __half* __restrict__ Whi,
    float* __restrict__ C, __half* __restrict__ Oh,
    int ldc, int bm, int bn) {
    const int tid = threadIdx.x;
    const int wid = tid >> 5, lane = tid & 31;
    const int wmr = wid >> 2, wnr = wid & 3;

    float acc[4][4][4];
#pragma unroll
    for (int i = 0; i < 4; i++)
#pragma unroll
        for (int j = 0; j < 4; j++)
#pragma unroll
            for (int r = 0; r < 4; r++) acc[i][j][r] = 0.f;

    const int lrow = lane & 15, lcol = (lane >> 4) * 8;

    auto fill = [&](int st, int k0) {
        char* base = gsm + st * GSTAGE;
#pragma unroll
        for (int i = 0; i < 4; i++) {
            int c = tid + i * 256;          // 0..1023 (row, 16B chunk)
            int row = c >> 3, kc = (c & 7) * 8;
            int so = (row * GROW + kc) * 2;
            size_t ga = (size_t)(bm + row) * 1024 + k0 + kc;
            size_t gb = (size_t)(bn + row) * 1024 + k0 + kc;
            cp16(base + so, Ah_g + ga);
            cp16(base + GTILE_B + so, Whi + gb);
        }
        CP_COMMIT();
    };

    fill(0, 0);
    for (int ch = 0; ch < 16; ch++) {
        if (ch + 1 < 16) {
            fill((ch + 1) & 1, (ch + 1) * 64);
            asm volatile("cp.async.wait_group 1;" ::: "memory");
        } else {
            asm volatile("cp.async.wait_group 0;" ::: "memory");
        }
        __syncthreads();
        char* base = gsm + (ch & 1) * GSTAGE;
        __half* sAh = (__half*)base;
        __half* sBh = (__half*)(base + GTILE_B);

#pragma unroll
        for (int ks = 0; ks < 64; ks += 16) {
            uint32_t bh[2][4];
#pragma unroll
            for (int p = 0; p < 2; p++) {
                int off = (wnr * 32 + p * 16 + lrow) * GROW + ks + lcol;
                ldsm_x4(bh[p], smem_u32(sBh + off));
            }
            uint32_t ah[2][4];
            {
                int off = (wmr * 64 + lrow) * GROW + ks + lcol;
                ldsm_x4(ah[0], smem_u32(sAh + off));
            }
#pragma unroll
            for (int mi = 0; mi < 4; mi++) {
                const int cur = mi & 1, nxt = cur ^ 1;
                if (mi < 3) {
                    int off = (wmr * 64 + (mi + 1) * 16 + lrow) * GROW + ks + lcol;
                    ldsm_x4(ah[nxt], smem_u32(sAh + off));
                }
#pragma unroll
                for (int ni = 0; ni < 4; ni++) {
                    int p = ni >> 1, q = ni & 1;
                    mma_f16(acc[mi][ni], ah[cur], bh[p][q], bh[p][q + 2]);
                }
            }
        }
        __syncthreads();
    }

    // ---- epilogue ----
    const int r_in = lane >> 2, c_in = (lane & 3) * 2;
#pragma unroll
    for (int mi = 0; mi < 4; mi++) {
#pragma unroll
        for (int ni = 0; ni < 4; ni++) {
            int m0 = bm + wmr * 64 + mi * 16 + r_in;
            int n  = bn + wnr * 32 + ni * 8 + c_in;
            float v0 = acc[mi][ni][0], v1 = acc[mi][ni][1];
            float v2 = acc[mi][ni][2], v3 = acc[mi][ni][3];
            if (MODE == 0) {
                *(float2*)(C + (size_t)m0 * ldc + n) = make_float2(v0, v1);
                *(float2*)(C + (size_t)(m0 + 8) * ldc + n) = make_float2(v2, v3);
            } else if (MODE == 4) {
                store_h(Oh, (size_t)m0 * ldc + n, v0, v1);
                store_h(Oh, (size_t)(m0 + 8) * ldc + n, v2, v3);
            } else {  // MODE 2: [b,h,s,d]
                int h = n >> 6, d = n & 63;
#pragma unroll
                for (int rr = 0; rr < 2; rr++) {
                    int m = m0 + rr * 8;
                    int b = m >> 11, s = m & 2047;
                    size_t off = ((size_t)((b * N_HEADS + h) * SEQ + s)) * HEAD_DIM + d;
                    store_h(Oh, off, acc[mi][ni][2 * rr], acc[mi][ni][2 * rr + 1]);
                }
            }
        }
    }
}

// fused Q/K/V projections: z=0 -> Q, z=1 -> K, z=2 -> V-transposed
__global__ __launch_bounds__(256, 2)
void qkv_gemm(const __half* __restrict__ xh, const __half* __restrict__ wh,
              __half* __restrict__ qh, __half* __restrict__ kh,
              __half* __restrict__ vth) {
    extern __shared__ char gsm[];
    const int z = blockIdx.z;
    if (z == 0) {
        gemm_body<2>(gsm, xh, wh, nullptr, qh, 0,
                     blockIdx.y * 128, blockIdx.x * 128);
    } else if (z == 1) {
        gemm_body<2>(gsm, xh, wh + WN, nullptr, kh, 0,
                     blockIdx.y * 128, blockIdx.x * 128);
    } else {
        // V transposed: C' = wv @ x^T -> [channel][token]
        gemm_body<4>(gsm, wh + 2 * (size_t)WN, xh, nullptr, vth, M_TOT,
                     blockIdx.x * 128, blockIdx.y * 128);
    }
}

// output projection: fp32 row-major
__global__ __launch_bounds__(256, 2)
void o_gemm(const __half* __restrict__ ah, const __half* __restrict__ wh,
            float* __restrict__ out) {
    extern __shared__ char gsm[];
    gemm_body<0>(gsm, ah, wh, out, nullptr, D_MODEL,
                 blockIdx.y * 128, blockIdx.x * 128);
}

// =================================================================
// Flash attention on mma.sync fp16, causal.
// CTA: 128 q rows x full head. 8 warps, warp = 16 q rows. Key tiles 64.
// cp.async 2-stage double-buffered K/V tiles. Q frags in registers.
// LPT: longest CTAs (high qt) launch first.
// =================================================================
#define ASROW 72
#define ABUF_B (64 * ASROW * 2)        // 9216 B per tile buffer
#define ASTAGE (2 * ABUF_B)            // 18432 B per stage (K, V)
#define ATTN_SMEM (2 * ASTAGE)         // 36864 B

__global__ __launch_bounds__(256, 2)
void attn_kernel(const __half* __restrict__ Qh,
                 const __half* __restrict__ Kh, const __half* __restrict__ Vh,
                 __half* __restrict__ Ohg) {
    extern __shared__ char asm_raw[];
    auto buf = [&](int st, int w) -> __half* {
        return (__half*)(asm_raw + st * ASTAGE + w * ABUF_B);
    };

    const int tid = threadIdx.x, wid = tid >> 5, lane = tid & 31;
    const int qt = (int)gridDim.x - 1 - (int)blockIdx.x;   // LPT: long CTAs first
    const int bh = blockIdx.y;
    const int b = bh >> 4, h = bh & 15;
    const int q0 = qt * 128;
    const size_t qkbase = (size_t)bh * SEQ * HEAD_DIM;
    const size_t vbase = (size_t)(h * 64) * 4096 + (size_t)b * 2048;

    const int lrow = lane & 15, lcol = (lane >> 4) * 8;
    const int rA = lane >> 2;
    const int tig2 = (lane & 3) * 2;

    // ---- stage Q into fragments via stage-0 scratch ----
#pragma unroll
    for (int i = 0; i < 4; i++) {
        int c = tid + i * 256;
        int row = c >> 3, cc = (c & 7) * 8;
        __half* dst = buf(0, row < 64 ? 0 : 1) + (row & 63) * ASROW + cc;
        *(uint4*)dst = *(const uint4*)(Qh + qkbase + (size_t)(q0 + row) * 64 + cc);
    }
    __syncthreads();
    uint32_t qfh[4][4];
    {
        int qr = wid * 16 + lrow;
        const __half* bq = buf(0, qr < 64 ? 0 : 1);
        int qrl = qr & 63;
#pragma unroll
        for (int ks = 0; ks < 4; ks++)
            ldsm_x4(qfh[ks], smem_u32(bq + qrl * ASROW + ks * 16 + lcol));
    }
    __syncthreads();   // scratch free before fillKV overwrites it

    auto fillKV = [&](int st, int k0) {
#pragma unroll
        for (int i = 0; i < 2; i++) {
            int c = tid + i * 256;
            int row = c >> 3, cc = (c & 7) * 8;
            int so = row * ASROW + cc;
            cp16(buf(st, 0) + so, Kh + qkbase + (size_t)(k0 + row) * 64 + cc);
            cp16(buf(st, 1) + so, Vh + vbase + (size_t)row * 4096 + k0 + cc);
        }
        CP_COMMIT();
    };

    float oacc[8][4];
#pragma unroll
    for (int i = 0; i < 8; i++)
#pragma unroll
        for (int j = 0; j < 4; j++) oacc[i][j] = 0.f;
    float mMA = -1e30f, mMB = -1e30f, lA = 0.f, lB = 0.f;

    const int nt = 2 * qt + 2;
    fillKV(0, 0);
    for (int jt = 0; jt < nt; jt++) {
        const int k0 = jt * 64;
        if (jt + 1 < nt) {
            fillKV((jt + 1) & 1, (jt + 1) * 64);
            asm volatile("cp.async.wait_group 1;" ::: "memory");
        } else {
            asm volatile("cp.async.wait_group 0;" ::: "memory");
        }
        __syncthreads();
        const int st = jt & 1;
        __half* sKh = buf(st, 0);
        __half* sVh = buf(st, 1);

        const int wrow0 = q0 + wid * 16;
        if (k0 <= wrow0 + 15) {
            // ---- scores S = Q K^T, pipelined K frags ----
            float sacc[8][4];
#pragma unroll
            for (int i = 0; i < 8; i++)
#pragma unroll
                for (int j = 0; j < 4; j++) sacc[i][j] = 0.f;
#pragma unroll
            for (int ks = 0; ks < 4; ks++) {
                uint32_t kfh[2][4];
                {
                    int off = lrow * ASROW + ks * 16 + lcol;   // p = 0
                    ldsm_x4(kfh[0], smem_u32(sKh + off));
                }
#pragma unroll
                for (int p = 0; p < 4; p++) {
                    const int cur = p & 1, nxt = cur ^ 1;
                    if (p < 3) {
                        int off = ((p + 1) * 16 + lrow) * ASROW + ks * 16 + lcol;
                        ldsm_x4(kfh[nxt], smem_u32(sKh + off));
                    }
#pragma unroll
                    for (int qq = 0; qq < 2; qq++) {
                        int ni = 2 * p + qq;
                        mma_f16(sacc[ni], qfh[ks], kfh[cur][qq], kfh[cur][qq + 2]);
                    }
                }
            }
            // ---- scale + causal mask ----
            const bool band = (k0 + 63 > wrow0);
            const int rowAg = wrow0 + rA, rowBg = rowAg + 8;
#pragma unroll
            for (int ni = 0; ni < 8; ni++) {
                int colb = k0 + ni * 8 + tig2;
#pragma unroll
                for (int e = 0; e < 4; e++) {
                    float s = sacc[ni][e] * 0.125f;
                    if (band) {
                        int col = colb + (e & 1);
                        int row = (e < 2) ? rowAg : rowBg;
                        if (col > row) s = -1e30f;
                    }
                    sacc[ni][e] = s;
                }
            }
            // ---- online softmax ----
            float mxA = -1e30f, mxB = -1e30f;
#pragma unroll
            for (int ni = 0; ni < 8; ni++) {
                mxA = fmaxf(mxA, fmaxf(sacc[ni][0], sacc[ni][1]));
                mxB = fmaxf(mxB, fmaxf(sacc[ni][2], sacc[ni][3]));
            }
            mxA = fmaxf(mxA, __shfl_xor_sync(0xffffffffu, mxA, 1));
            mxA = fmaxf(mxA, __shfl_xor_sync(0xffffffffu, mxA, 2));
            mxB = fmaxf(mxB, __shfl_xor_sync(0xffffffffu, mxB, 1));
            mxB = fmaxf(mxB, __shfl_xor_sync(0xffffffffu, mxB, 2));
            float mnA = fmaxf(mMA, mxA), mnB = fmaxf(mMB, mxB);
            float scA = __expf(mMA - mnA), scB = __expf(mMB - mnB);
            mMA = mnA; mMB = mnB;
            float suA = 0.f, suB = 0.f;
#pragma unroll
            for (int ni = 0; ni < 8; ni++) {
                sacc[ni][0] = __expf(sacc[ni][0] - mnA); suA += sacc[ni][0];
                sacc[ni][1] = __expf(sacc[ni][1] - mnA); suA += sacc[ni][1];
                sacc[ni][2] = __expf(sacc[ni][2] - mnB); suB += sacc[ni][2];
                sacc[ni][3] = __expf(sacc[ni][3] - mnB); suB += sacc[ni][3];
            }
            suA += __shfl_xor_sync(0xffffffffu, suA, 1);
            suA += __shfl_xor_sync(0xffffffffu, suA, 2);
            suB += __shfl_xor_sync(0xffffffffu, suB, 1);
            suB += __shfl_xor_sync(0xffffffffu, suB, 2);
            lA = lA * scA + suA;
            lB = lB * scB + suB;
#pragma unroll
            for (int ni = 0; ni < 8; ni++) {
                oacc[ni][0] *= scA; oacc[ni][1] *= scA;
                oacc[ni][2] *= scB; oacc[ni][3] *= scB;
            }
            // ---- O += P * V^T, pipelined V frags ----
#pragma unroll
            for (int j = 0; j < 4; j++) {
                uint32_t Ph[4];
                Ph[0] = pack_h(sacc[2 * j][0],     sacc[2 * j][1]);
                Ph[1] = pack_h(sacc[2 * j][2],     sacc[2 * j][3]);
                Ph[2] = pack_h(sacc[2 * j + 1][0], sacc[2 * j + 1][1]);
                Ph[3] = pack_h(sacc[2 * j + 1][2], sacc[2 * j + 1][3]);
                uint32_t vfh[2][4];
                {
                    int off = lrow * ASROW + j * 16 + lcol;    // p = 0
                    ldsm_x4(vfh[0], smem_u32(sVh + off));
                }
#pragma unroll
                for (int p = 0; p < 4; p++) {
                    const int cur = p & 1, nxt = cur ^ 1;
                    if (p < 3) {
                        int off = ((p + 1) * 16 + lrow) * ASROW + j * 16 + lcol;
                        ldsm_x4(vfh[nxt], smem_u32(sVh + off));
                    }
#pragma unroll
                    for (int qq = 0; qq < 2; qq++) {
                        int ni = 2 * p + qq;
                        mma_f16(oacc[ni], Ph, vfh[cur][qq], vfh[cur][qq + 2]);
                    }
                }
            }
        }
        __syncthreads();   // all warps done with stage st before it is refilled
    }

    // ---- normalize + store fp16 to [m][1024] ----
    float iA = 1.f / lA, iB = 1.f / lB;
    int sA = q0 + wid * 16 + rA;
    size_t rowA_off = ((size_t)b * SEQ + sA) * D_MODEL + h * 64;
    size_t rowB_off = rowA_off + (size_t)8 * D_MODEL;
#pragma unroll
    for (int ni = 0; ni < 8; ni++) {
        int n = ni * 8 + tig2;
        store_h(Ohg, rowA_off + n, oacc[ni][0] * iA, oacc[ni][1] * iA);
        store_h(Ohg, rowB_off + n, oacc[ni][2] * iB, oacc[ni][3] * iB);
    }
}

// =================================================================
// launch
// =================================================================
extern "C" void kernel_launch(void* const* d_in, const int* in_sizes, int n_in,
                              void* d_out, int out_size) {
    const float* x  = (const float*)d_in[0];
    const float* wq = (const float*)d_in[1];
    const float* wk = (const float*)d_in[2];
    const float* wv = (const float*)d_in[3];
    const float* wo = (const float*)d_in[4];
    float* out = (float*)d_out;

    __half *xh, *wh, *qh, *kh, *vth, *ah;
    cudaGetSymbolAddress((void**)&xh, g_x_hi);
    cudaGetSymbolAddress((void**)&wh, g_w_hi);
    cudaGetSymbolAddress((void**)&qh, g_qh);
    cudaGetSymbolAddress((void**)&kh, g_kh);
    cudaGetSymbolAddress((void**)&vth, g_vth);
    cudaGetSymbolAddress((void**)&ah, g_ah);

    cudaFuncSetAttribute(qkv_gemm,
                         cudaFuncAttributeMaxDynamicSharedMemorySize, GEMM_SMEM);
    cudaFuncSetAttribute(o_gemm,
                         cudaFuncAttributeMaxDynamicSharedMemorySize, GEMM_SMEM);
    cudaFuncSetAttribute(attn_kernel,
                         cudaFuncAttributeMaxDynamicSharedMemorySize, ATTN_SMEM);

    // one fused split for x + all 4 weights (fp16, no lo terms)
    split_all<<<(XF4 + 4 * WF4 + 255) / 256, 256>>>(x, wq, wk, wv, wo, xh, wh);

    // fused Q/K/V projections (z = 0,1,2)
    dim3 g_qkv(8, 32, 3);
    qkv_gemm<<<g_qkv, 256, GEMM_SMEM>>>(xh, wh, qh, kh, vth);

    // attention -> fp16 [m][1024]
    dim3 g_at(SEQ / 128, BATCH * N_HEADS);    // (16, 32), LPT order inside
    attn_kernel<<<g_at, 256, ATTN_SMEM>>>(qh, kh, vth, ah);

    // output projection -> fp32 out
    dim3 g_o(8, 32);
    o_gemm<<<g_o, 256, GEMM_SMEM>>>(ah, wh + 3 * (size_t)WN, out);
}

// round 15
// speedup vs baseline: 2.7670x; 1.1225x over previous
#include <cuda_runtime.h>
#include <cuda_fp16.h>
#include <cstdint>
#include <math.h>

#define D_MODEL 1024
#define N_HEADS 16
#define HEAD_DIM 64
#define BATCH 2
#define SEQ 2048
#define M_TOT (BATCH * SEQ)   // 4096
#define WN (D_MODEL * D_MODEL)

// ---------------- scratch (no allocations allowed) ----------------
__device__ __half g_x_hi[M_TOT * D_MODEL];
__device__ __half g_w_hi[4 * WN];   // wq,wk,wv,wo
__device__ __half g_qh[M_TOT * D_MODEL];    // [b,h,s,d]
__device__ __half g_kh[M_TOT * D_MODEL];    // [b,h,s,d]
__device__ __half g_vth[M_TOT * D_MODEL];   // [h*64+d][b*2048+s]
__device__ __half g_ah[M_TOT * D_MODEL];    // [m][1024]
__device__ int g_ctr_qkv;                   // dynamic tile counters
__device__ int g_ctr_at;

// =================== portable PTX helpers ===================
__device__ __forceinline__ uint32_t smem_u32(const void* p) {
    uint32_t a;
    asm("{ .reg .u64 t; cvta.to.shared.u64 t, %1; cvt.u32.u64 %0, t; }"
        : "=r"(a) : "l"(p));
    return a;
}

__device__ __forceinline__ void ldsm_x4(uint32_t* r, uint32_t addr) {
    asm volatile("ldmatrix.sync.aligned.m8n8.x4.shared.b16 {%0,%1,%2,%3}, [%4];"
                 : "=r"(r[0]), "=r"(r[1]), "=r"(r[2]), "=r"(r[3]) : "r"(addr));
}

// D += A * B  (m16n8k16, fp16 in, fp32 acc)
__device__ __forceinline__ void mma_f16(float* d, const uint32_t* a,
                                        uint32_t b0, uint32_t b1) {
    asm volatile(
        "mma.sync.aligned.m16n8k16.row.col.f32.f16.f16.f32 "
        "{%0,%1,%2,%3}, {%4,%5,%6,%7}, {%8,%9}, {%0,%1,%2,%3};"
        : "+f"(d[0]), "+f"(d[1]), "+f"(d[2]), "+f"(d[3])
        : "r"(a[0]), "r"(a[1]), "r"(a[2]), "r"(a[3]), "r"(b0), "r"(b1));
}

__device__ __forceinline__ void cp16(void* dst_smem, const void* src) {
    uint32_t d = smem_u32(dst_smem);
    asm volatile("cp.async.cg.shared.global [%0], [%1], 16;" :: "r"(d), "l"(src) : "memory");
}
#define CP_COMMIT() asm volatile("cp.async.commit_group;" ::: "memory")

__device__ __forceinline__ uint32_t pack_h(float v0, float v1) {
    __half2 h = __floats2half2_rn(v0, v1);
    return *(uint32_t*)&h;
}
__device__ __forceinline__ void store_h(__half* Oh, size_t off, float v0, float v1) {
    *(__half2*)(Oh + off) = __floats2half2_rn(v0, v1);
}

// =================================================================
// fused split: x + 4 weights -> fp16; also resets tile counters
// =================================================================
#define XF4 (M_TOT * D_MODEL / 4)   // 1048576
#define WF4 (WN / 4)                // 262144

__global__ __launch_bounds__(256)
void split_all(const float* __restrict__ x, const float* __restrict__ wq,
               const float* __restrict__ wk, const float* __restrict__ wv,
               const float* __restrict__ wo,
               __half* __restrict__ xh, __half* __restrict__ wh) {
    if (blockIdx.x == 0 && threadIdx.x == 0) {
        g_ctr_qkv = 0;
        g_ctr_at = 0;
    }
    int i = blockIdx.x * 256 + threadIdx.x;
    const float* src;
    __half* hi;
    int off;
    if (i < XF4) {
        src = x; hi = xh; off = i;
    } else {
        int j = i - XF4;
        int w = j >> 18;            // /WF4
        off = j & (WF4 - 1);
        src = (w == 0) ? wq : (w == 1) ? wk : (w == 2) ? wv : wo;
        hi = wh + (size_t)w * WN;
    }
    float4 v = ((const float4*)src)[off];
    __half2 h0 = __floats2half2_rn(v.x, v.y);
    __half2 h1 = __floats2half2_rn(v.z, v.w);
    ((uint2*)hi)[off] = make_uint2(*(uint32_t*)&h0, *(uint32_t*)&h1);
}

// =================================================================
// GEMM body: C tile = A[.,1024] @ W[.,1024]^T, plain fp16, fp32 acc.
// cp.async 2-stage, BK=64, 128x128 tile, 8 warps (2m x 4n).
// MODE 0: fp32 row-major C (ldc)
// MODE 2: fp16 -> [b,h,s,d] head layout (Q, K)
// MODE 4: fp16 row-major (ldc)          (V-transposed)
// =================================================================
#define GROW 72                        // smem row stride in halves (64 + 8 pad)
#define GTILE_B (128 * GROW * 2)       // 18432 B per tile
#define GSTAGE (2 * GTILE_B)           // 36864 B per stage (A, B)
#define GEMM_SMEM (2 * GSTAGE)         // 73728 B

template <int MODE>
__device__ __forceinline__ void gemm_body(
    char* gsm,
    const __half* __restrict__ Ah_g, const __half* __restrict__ Whi,
    float* __restrict__ C, __half* __restrict__ Oh,
    int ldc, int bm, int bn) {
    const int tid = threadIdx.x;
    const int wid = tid >> 5, lane = tid & 31;
    const int wmr = wid >> 2, wnr = wid & 3;

    float acc[4][4][4];
#pragma unroll
    for (int i = 0; i < 4; i++)
#pragma unroll
        for (int j = 0; j < 4; j++)
#pragma unroll
            for (int r = 0; r < 4; r++) acc[i][j][r] = 0.f;

    const int lrow = lane & 15, lcol = (lane >> 4) * 8;

    auto fill = [&](int st, int k0) {
        char* base = gsm + st * GSTAGE;
#pragma unroll
        for (int i = 0; i < 4; i++) {
            int c = tid + i * 256;          // 0..1023 (row, 16B chunk)
            int row = c >> 3, kc = (c & 7) * 8;
            int so = (row * GROW + kc) * 2;
            size_t ga = (size_t)(bm + row) * 1024 + k0 + kc;
            size_t gb = (size_t)(bn + row) * 1024 + k0 + kc;
            cp16(base + so, Ah_g + ga);
            cp16(base + GTILE_B + so, Whi + gb);
        }
        CP_COMMIT();
    };

    fill(0, 0);
    for (int ch = 0; ch < 16; ch++) {
        if (ch + 1 < 16) {
            fill((ch + 1) & 1, (ch + 1) * 64);
            asm volatile("cp.async.wait_group 1;" ::: "memory");
        } else {
            asm volatile("cp.async.wait_group 0;" ::: "memory");
        }
        __syncthreads();
        char* base = gsm + (ch & 1) * GSTAGE;
        __half* sAh = (__half*)base;
        __half* sBh = (__half*)(base + GTILE_B);

#pragma unroll
        for (int ks = 0; ks < 64; ks += 16) {
            uint32_t bh[2][4];
#pragma unroll
            for (int p = 0; p < 2; p++) {
                int off = (wnr * 32 + p * 16 + lrow) * GROW + ks + lcol;
                ldsm_x4(bh[p], smem_u32(sBh + off));
            }
            uint32_t ah[2][4];
            {
                int off = (wmr * 64 + lrow) * GROW + ks + lcol;
                ldsm_x4(ah[0], smem_u32(sAh + off));
            }
#pragma unroll
            for (int mi = 0; mi < 4; mi++) {
                const int cur = mi & 1, nxt = cur ^ 1;
                if (mi < 3) {
                    int off = (wmr * 64 + (mi + 1) * 16 + lrow) * GROW + ks + lcol;
                    ldsm_x4(ah[nxt], smem_u32(sAh + off));
                }
#pragma unroll
                for (int ni = 0; ni < 4; ni++) {
                    int p = ni >> 1, q = ni & 1;
                    mma_f16(acc[mi][ni], ah[cur], bh[p][q], bh[p][q + 2]);
                }
            }
        }
        __syncthreads();
    }

    // ---- epilogue ----
    const int r_in = lane >> 2, c_in = (lane & 3) * 2;
#pragma unroll
    for (int mi = 0; mi < 4; mi++) {
#pragma unroll
        for (int ni = 0; ni < 4; ni++) {
            int m0 = bm + wmr * 64 + mi * 16 + r_in;
            int n  = bn + wnr * 32 + ni * 8 + c_in;
            float v0 = acc[mi][ni][0], v1 = acc[mi][ni][1];
            float v2 = acc[mi][ni][2], v3 = acc[mi][ni][3];
            if (MODE == 0) {
                *(float2*)(C + (size_t)m0 * ldc + n) = make_float2(v0, v1);
                *(float2*)(C + (size_t)(m0 + 8) * ldc + n) = make_float2(v2, v3);
            } else if (MODE == 4) {
                store_h(Oh, (size_t)m0 * ldc + n, v0, v1);
                store_h(Oh, (size_t)(m0 + 8) * ldc + n, v2, v3);
            } else {  // MODE 2: [b,h,s,d]
                int h = n >> 6, d = n & 63;
#pragma unroll
                for (int rr = 0; rr < 2; rr++) {
                    int m = m0 + rr * 8;
                    int b = m >> 11, s = m & 2047;
                    size_t off = ((size_t)((b * N_HEADS + h) * SEQ + s)) * HEAD_DIM + d;
                    store_h(Oh, off, acc[mi][ni][2 * rr], acc[mi][ni][2 * rr + 1]);
                }
            }
        }
    }
}

// persistent fused Q/K/V projections: 768 tiles, dynamic stealing
#define QKV_TILES 768
#define PERS_CTAS 296

__global__ __launch_bounds__(256, 2)
void qkv_gemm(const __half* __restrict__ xh, const __half* __restrict__ wh,
              __half* __restrict__ qh, __half* __restrict__ kh,
              __half* __restrict__ vth) {
    extern __shared__ char gsm[];
    __shared__ int s_tile;
    const int tid = threadIdx.x;

    while (true) {
        if (tid == 0) s_tile = atomicAdd(&g_ctr_qkv, 1);
        __syncthreads();
        int t = s_tile;
        if (t >= QKV_TILES) return;
        int z = t >> 8;             // 0..2
        int r = t & 255;
        int by = r >> 3, bx = r & 7;
        if (z == 0) {
            gemm_body<2>(gsm, xh, wh, nullptr, qh, 0, by * 128, bx * 128);
        } else if (z == 1) {
            gemm_body<2>(gsm, xh, wh + WN, nullptr, kh, 0, by * 128, bx * 128);
        } else {
            // V transposed: C' = wv @ x^T -> [channel][token]
            gemm_body<4>(gsm, wh + 2 * (size_t)WN, xh, nullptr, vth, M_TOT,
                         bx * 128, by * 128);
        }
    }
}

// output projection: fp32 row-major (single wave, static)
__global__ __launch_bounds__(256, 2)
void o_gemm(const __half* __restrict__ ah, const __half* __restrict__ wh,
            float* __restrict__ out) {
    extern __shared__ char gsm[];
    gemm_body<0>(gsm, ah, wh, out, nullptr, D_MODEL,
                 blockIdx.y * 128, blockIdx.x * 128);
}

// =================================================================
// Flash attention on mma.sync fp16, causal. Persistent + dynamic LPT.
// Work item w: qt = 15 - (w>>5) (long first), bh = w & 31.
// CTA: 128 q rows x full head. 8 warps, warp = 16 q rows. Key tiles 64.
// cp.async 2-stage double-buffered K/V tiles. Q frags in registers.
// =================================================================
#define ASROW 72
#define ABUF_B (64 * ASROW * 2)        // 9216 B per tile buffer
#define ASTAGE (2 * ABUF_B)            // 18432 B per stage (K, V)
#define ATTN_SMEM (2 * ASTAGE)         // 36864 B
#define AT_WORK 512

__global__ __launch_bounds__(256, 2)
void attn_kernel(const __half* __restrict__ Qh,
                 const __half* __restrict__ Kh, const __half* __restrict__ Vh,
                 __half* __restrict__ Ohg) {
    extern __shared__ char asm_raw[];
    __shared__ int s_work;
    auto buf = [&](int st, int w) -> __half* {
        return (__half*)(asm_raw + st * ASTAGE + w * ABUF_B);
    };

    const int tid = threadIdx.x, wid = tid >> 5, lane = tid & 31;
    const int lrow = lane & 15, lcol = (lane >> 4) * 8;
    const int rA = lane >> 2;
    const int tig2 = (lane & 3) * 2;

    while (true) {
        if (tid == 0) s_work = atomicAdd(&g_ctr_at, 1);
        __syncthreads();
        int w = s_work;
        if (w >= AT_WORK) return;
        const int qt = 15 - (w >> 5);       // LPT: long CTAs first
        const int bh = w & 31;
        const int b = bh >> 4, h = bh & 15;
        const int q0 = qt * 128;
        const size_t qkbase = (size_t)bh * SEQ * HEAD_DIM;
        const size_t vbase = (size_t)(h * 64) * 4096 + (size_t)b * 2048;

        // ---- stage Q into fragments via stage-0 scratch ----
#pragma unroll
        for (int i = 0; i < 4; i++) {
            int c = tid + i * 256;
            int row = c >> 3, cc = (c & 7) * 8;
            __half* dst = buf(0, row < 64 ? 0 : 1) + (row & 63) * ASROW + cc;
            *(uint4*)dst = *(const uint4*)(Qh + qkbase + (size_t)(q0 + row) * 64 + cc);
        }
        __syncthreads();
        uint32_t qfh[4][4];
        {
            int qr = wid * 16 + lrow;
            const __half* bq = buf(0, qr < 64 ? 0 : 1);
            int qrl = qr & 63;
#pragma unroll
            for (int ks = 0; ks < 4; ks++)
                ldsm_x4(qfh[ks], smem_u32(bq + qrl * ASROW + ks * 16 + lcol));
        }
        __syncthreads();   // scratch free before fillKV overwrites it

        auto fillKV = [&](int st, int k0) {
#pragma unroll
            for (int i = 0; i < 2; i++) {
                int c = tid + i * 256;
                int row = c >> 3, cc = (c & 7) * 8;
                int so = row * ASROW + cc;
                cp16(buf(st, 0) + so, Kh + qkbase + (size_t)(k0 + row) * 64 + cc);
                cp16(buf(st, 1) + so, Vh + vbase + (size_t)row * 4096 + k0 + cc);
            }
            CP_COMMIT();
        };

        float oacc[8][4];
#pragma unroll
        for (int i = 0; i < 8; i++)
#pragma unroll
            for (int j = 0; j < 4; j++) oacc[i][j] = 0.f;
        float mMA = -1e30f, mMB = -1e30f, lA = 0.f, lB = 0.f;

        const int nt = 2 * qt + 2;
        fillKV(0, 0);
        for (int jt = 0; jt < nt; jt++) {
            const int k0 = jt * 64;
            if (jt + 1 < nt) {
                fillKV((jt + 1) & 1, (jt + 1) * 64);
                asm volatile("cp.async.wait_group 1;" ::: "memory");
            } else {
                asm volatile("cp.async.wait_group 0;" ::: "memory");
            }
            __syncthreads();
            const int st = jt & 1;
            __half* sKh = buf(st, 0);
            __half* sVh = buf(st, 1);

            const int wrow0 = q0 + wid * 16;
            if (k0 <= wrow0 + 15) {
                // ---- scores S = Q K^T, pipelined K frags ----
                float sacc[8][4];
#pragma unroll
                for (int i = 0; i < 8; i++)
#pragma unroll
                    for (int j = 0; j < 4; j++) sacc[i][j] = 0.f;
#pragma unroll
                for (int ks = 0; ks < 4; ks++) {
                    uint32_t kfh[2][4];
                    {
                        int off = lrow * ASROW + ks * 16 + lcol;   // p = 0
                        ldsm_x4(kfh[0], smem_u32(sKh + off));
                    }
#pragma unroll
                    for (int p = 0; p < 4; p++) {
                        const int cur = p & 1, nxt = cur ^ 1;
                        if (p < 3) {
                            int off = ((p + 1) * 16 + lrow) * ASROW + ks * 16 + lcol;
                            ldsm_x4(kfh[nxt], smem_u32(sKh + off));
                        }
#pragma unroll
                        for (int qq = 0; qq < 2; qq++) {
                            int ni = 2 * p + qq;
                            mma_f16(sacc[ni], qfh[ks], kfh[cur][qq], kfh[cur][qq + 2]);
                        }
                    }
                }
                // ---- scale + causal mask ----
                const bool band = (k0 + 63 > wrow0);
                const int rowAg = wrow0 + rA, rowBg = rowAg + 8;
#pragma unroll
                for (int ni = 0; ni < 8; ni++) {
                    int colb = k0 + ni * 8 + tig2;
#pragma unroll
                    for (int e = 0; e < 4; e++) {
                        float s = sacc[ni][e] * 0.125f;
                        if (band) {
                            int col = colb + (e & 1);
                            int row = (e < 2) ? rowAg : rowBg;
                            if (col > row) s = -1e30f;
                        }
                        sacc[ni][e] = s;
                    }
                }
                // ---- online softmax ----
                float mxA = -1e30f, mxB = -1e30f;
#pragma unroll
                for (int ni = 0; ni < 8; ni++) {
                    mxA = fmaxf(mxA, fmaxf(sacc[ni][0], sacc[ni][1]));
                    mxB = fmaxf(mxB, fmaxf(sacc[ni][2], sacc[ni][3]));
                }
                mxA = fmaxf(mxA, __shfl_xor_sync(0xffffffffu, mxA, 1));
                mxA = fmaxf(mxA, __shfl_xor_sync(0xffffffffu, mxA, 2));
                mxB = fmaxf(mxB, __shfl_xor_sync(0xffffffffu, mxB, 1));
                mxB = fmaxf(mxB, __shfl_xor_sync(0xffffffffu, mxB, 2));
                float mnA = fmaxf(mMA, mxA), mnB = fmaxf(mMB, mxB);
                float scA = __expf(mMA - mnA), scB = __expf(mMB - mnB);
                mMA = mnA; mMB = mnB;
                float suA = 0.f, suB = 0.f;
#pragma unroll
                for (int ni = 0; ni < 8; ni++) {
                    sacc[ni][0] = __expf(sacc[ni][0] - mnA); suA += sacc[ni][0];
                    sacc[ni][1] = __expf(sacc[ni][1] - mnA); suA += sacc[ni][1];
                    sacc[ni][2] = __expf(sacc[ni][2] - mnB); suB += sacc[ni][2];
                    sacc[ni][3] = __expf(sacc[ni][3] - mnB); suB += sacc[ni][3];
                }
                suA += __shfl_xor_sync(0xffffffffu, suA, 1);
                suA += __shfl_xor_sync(0xffffffffu, suA, 2);
                suB += __shfl_xor_sync(0xffffffffu, suB, 1);
                suB += __shfl_xor_sync(0xffffffffu, suB, 2);
                lA = lA * scA + suA;
                lB = lB * scB + suB;
#pragma unroll
                for (int ni = 0; ni < 8; ni++) {
                    oacc[ni][0] *= scA; oacc[ni][1] *= scA;
                    oacc[ni][2] *= scB; oacc[ni][3] *= scB;
                }
                // ---- O += P * V^T, pipelined V frags ----
#pragma unroll
                for (int j = 0; j < 4; j++) {
                    uint32_t Ph[4];
                    Ph[0] = pack_h(sacc[2 * j][0],     sacc[2 * j][1]);
                    Ph[1] = pack_h(sacc[2 * j][2],     sacc[2 * j][3]);
                    Ph[2] = pack_h(sacc[2 * j + 1][0], sacc[2 * j + 1][1]);
                    Ph[3] = pack_h(sacc[2 * j + 1][2], sacc[2 * j + 1][3]);
                    uint32_t vfh[2][4];
                    {
                        int off = lrow * ASROW + j * 16 + lcol;    // p = 0
                        ldsm_x4(vfh[0], smem_u32(sVh + off));
                    }
#pragma unroll
                    for (int p = 0; p < 4; p++) {
                        const int cur = p & 1, nxt = cur ^ 1;
                        if (p < 3) {
                            int off = ((p + 1) * 16 + lrow) * ASROW + j * 16 + lcol;
                            ldsm_x4(vfh[nxt], smem_u32(sVh + off));
                        }
#pragma unroll
                        for (int qq = 0; qq < 2; qq++) {
                            int ni = 2 * p + qq;
                            mma_f16(oacc[ni], Ph, vfh[cur][qq], vfh[cur][qq + 2]);
                        }
                    }
                }
            }
            __syncthreads();   // all warps done with stage st before refill
        }

        // ---- normalize + store fp16 to [m][1024] ----
        float iA = 1.f / lA, iB = 1.f / lB;
        int sA = q0 + wid * 16 + rA;
        size_t rowA_off = ((size_t)b * SEQ + sA) * D_MODEL + h * 64;
        size_t rowB_off = rowA_off + (size_t)8 * D_MODEL;
#pragma unroll
        for (int ni = 0; ni < 8; ni++) {
            int n = ni * 8 + tig2;
            store_h(Ohg, rowA_off + n, oacc[ni][0] * iA, oacc[ni][1] * iA);
            store_h(Ohg, rowB_off + n, oacc[ni][2] * iB, oacc[ni][3] * iB);
        }
    }
}

// =================================================================
// launch
// =================================================================
extern "C" void kernel_launch(void* const* d_in, const int* in_sizes, int n_in,
                              void* d_out, int out_size) {
    const float* x  = (const float*)d_in[0];
    const float* wq = (const float*)d_in[1];
    const float* wk = (const float*)d_in[2];
    const float* wv = (const float*)d_in[3];
    const float* wo = (const float*)d_in[4];
    float* out = (float*)d_out;

    __half *xh, *wh, *qh, *kh, *vth, *ah;
    cudaGetSymbolAddress((void**)&xh, g_x_hi);
    cudaGetSymbolAddress((void**)&wh, g_w_hi);
    cudaGetSymbolAddress((void**)&qh, g_qh);
    cudaGetSymbolAddress((void**)&kh, g_kh);
    cudaGetSymbolAddress((void**)&vth, g_vth);
    cudaGetSymbolAddress((void**)&ah, g_ah);

    cudaFuncSetAttribute(qkv_gemm,
                         cudaFuncAttributeMaxDynamicSharedMemorySize, GEMM_SMEM);
    cudaFuncSetAttribute(o_gemm,
                         cudaFuncAttributeMaxDynamicSharedMemorySize, GEMM_SMEM);
    cudaFuncSetAttribute(attn_kernel,
                         cudaFuncAttributeMaxDynamicSharedMemorySize, ATTN_SMEM);

    // one fused split for x + all 4 weights; also resets tile counters
    split_all<<<(XF4 + 4 * WF4 + 255) / 256, 256>>>(x, wq, wk, wv, wo, xh, wh);

    // persistent fused Q/K/V projections (dynamic tile stealing)
    qkv_gemm<<<PERS_CTAS, 256, GEMM_SMEM>>>(xh, wh, qh, kh, vth);

    // persistent attention (dynamic LPT work stealing) -> fp16 [m][1024]
    attn_kernel<<<PERS_CTAS, 256, ATTN_SMEM>>>(qh, kh, vth, ah);

    // output projection -> fp32 out
    dim3 g_o(8, 32);
    o_gemm<<<g_o, 256, GEMM_SMEM>>>(ah, wh + 3 * (size_t)WN, out);
}